// round 3
// baseline (speedup 1.0000x reference)
#include <cuda_runtime.h>
#include <cuda_bf16.h>
#include <cstddef>

// ---------------- scratch (device globals; no allocation allowed) ----------------
__device__ float g_bufA[16u*64u*128u*128u];   // 16.78M floats (e1 out / dt1 out)
__device__ float g_bufB[16u*128u*64u*64u];    // 8.39M
__device__ float g_bufC[16u*128u*64u*64u];
__device__ float g_bufD[16u*128u*64u*64u];
__device__ float g_r  [16u*64u*64u*64u];      // residual tokens (NCHW view)
__device__ float g_q  [16u*64u*64u*64u];      // quantized accumulation (NCHW view)
__device__ float g_cnorm[4*512];
__device__ float g_partials[4*256];

#define TW 16
#define OCB 16

// ---------------- tiled direct convolution (stride S, kernel K), pure fp32 ----------------
// Accumulation order per output: k = (ci, ky, kx) ascending, single fp32 accumulator,
// FFMA (single rounding per step) — matches cuDNN implicit-gemm NCHW/KCRS ordering.
// act: 0=none, 1=leaky_relu(0.01), 2=relu.  bias/resid may be nullptr.
template<int K, int S>
__global__ __launch_bounds__(256)
void conv_tiled(const float* __restrict__ in, const float* __restrict__ wt,
                const float* __restrict__ bias, const float* __restrict__ resid,
                float* __restrict__ out,
                int N, int Cin, int Hin, int Win, int Cout, int Hout, int Wout,
                int pad, int act)
{
    constexpr int IW = TW*S + K - S;
    constexpr int KK = K*K;
    __shared__ float sIn[IW*IW];
    __shared__ __align__(16) float sWt[KK*OCB];   // [tap][oc]

    const int chunks = Cout / OCB;
    const int n   = blockIdx.z / chunks;
    const int ocb = (blockIdx.z % chunks) * OCB;
    const int ox0 = blockIdx.x * TW, oy0 = blockIdx.y * TW;
    const int tx = threadIdx.x & 15, ty = threadIdx.x >> 4;
    const int ix0 = ox0*S - pad, iy0 = oy0*S - pad;

    float acc[OCB];
    #pragma unroll
    for (int o = 0; o < OCB; o++) acc[o] = 0.f;

    for (int ci = 0; ci < Cin; ci++) {
        const float* ip = in + ((size_t)(n*Cin + ci) * Hin) * Win;
        for (int i = threadIdx.x; i < IW*IW; i += 256) {
            int ry = i / IW, rx = i - ry*IW;
            int gy = iy0 + ry, gx = ix0 + rx;
            float v = 0.f;
            if ((unsigned)gy < (unsigned)Hin && (unsigned)gx < (unsigned)Win)
                v = __ldg(ip + (size_t)gy*Win + gx);
            sIn[i] = v;
        }
        for (int i = threadIdx.x; i < KK*OCB; i += 256) {
            int oc = i & (OCB-1), kk = i >> 4;
            sWt[i] = __ldg(wt + ((size_t)(ocb+oc)*Cin + ci)*KK + kk);
        }
        __syncthreads();
        #pragma unroll
        for (int ky = 0; ky < K; ky++) {
            #pragma unroll
            for (int kx = 0; kx < K; kx++) {
                float s = sIn[(ty*S + ky)*IW + tx*S + kx];
                const float4* wp = (const float4*)(sWt + (ky*K + kx)*OCB);
                #pragma unroll
                for (int j4 = 0; j4 < OCB/4; j4++) {
                    float4 w = wp[j4];
                    acc[j4*4+0] = fmaf(w.x, s, acc[j4*4+0]);
                    acc[j4*4+1] = fmaf(w.y, s, acc[j4*4+1]);
                    acc[j4*4+2] = fmaf(w.z, s, acc[j4*4+2]);
                    acc[j4*4+3] = fmaf(w.w, s, acc[j4*4+3]);
                }
            }
        }
        __syncthreads();
    }

    const int oy = oy0 + ty, ox = ox0 + tx;
    #pragma unroll
    for (int o = 0; o < OCB; o++) {
        int c = ocb + o;
        float v = acc[o];
        if (bias)  v = __fadd_rn(v, __ldg(bias + c));
        size_t oi = (((size_t)n*Cout + c)*Hout + oy)*Wout + ox;
        if (resid) v = __fadd_rn(v, resid[oi]);
        if (act == 1)      v = (v > 0.f) ? v : __fmul_rn(0.01f, v);
        else if (act == 2) v = (v > 0.f) ? v : 0.f;
        out[oi] = v;
    }
}

// ---------------- transposed conv (k=4, s=2, p=1), torch weight layout (in,out,4,4) ----------------
template<int OCBt>
__global__ __launch_bounds__(256)
void convT_tiled(const float* __restrict__ in, const float* __restrict__ wt,
                 const float* __restrict__ bias, float* __restrict__ out,
                 int N, int Cin, int Hin, int Win, int Cout, int act)
{
    const int IW = 10;
    __shared__ float sIn[IW*IW];
    __shared__ __align__(16) float sWt[16*OCBt];   // [tap][oc]

    const int Hout = Hin*2, Wout = Win*2;
    const int chunks = Cout / OCBt;
    const int n   = blockIdx.z / chunks;
    const int ocb = (blockIdx.z % chunks) * OCBt;
    const int ox0 = blockIdx.x*16, oy0 = blockIdx.y*16;
    const int tx = threadIdx.x & 15, ty = threadIdx.x >> 4;
    const int oy = oy0 + ty, ox = ox0 + tx;
    const int iyb = oy0/2 - 1, ixb = ox0/2 - 1;
    const int ky0 = (oy + 1) & 1, kx0 = (ox + 1) & 1;
    const int iyl0 = ((oy + 1 - ky0) >> 1) - iyb;   // 1..9
    const int iyl1 = iyl0 - 1;                      // 0..8
    const int ixl0 = ((ox + 1 - kx0) >> 1) - ixb;
    const int ixl1 = ixl0 - 1;
    const int k00 = ky0*4 + kx0,       k01 = ky0*4 + kx0 + 2;
    const int k10 = (ky0+2)*4 + kx0,   k11 = (ky0+2)*4 + kx0 + 2;

    float acc[OCBt];
    #pragma unroll
    for (int o = 0; o < OCBt; o++) acc[o] = 0.f;

    for (int ci = 0; ci < Cin; ci++) {
        const float* ip = in + ((size_t)(n*Cin + ci) * Hin) * Win;
        for (int i = threadIdx.x; i < IW*IW; i += 256) {
            int ry = i / IW, rx = i - ry*IW;
            int gy = iyb + ry, gx = ixb + rx;
            float v = 0.f;
            if ((unsigned)gy < (unsigned)Hin && (unsigned)gx < (unsigned)Win)
                v = __ldg(ip + (size_t)gy*Win + gx);
            sIn[i] = v;
        }
        for (int i = threadIdx.x; i < 16*OCBt; i += 256) {
            int oc = i % OCBt, kk = i / OCBt;
            sWt[i] = __ldg(wt + ((size_t)ci*Cout + (ocb+oc))*16 + kk);
        }
        __syncthreads();
        float s00 = sIn[iyl0*IW + ixl0];
        float s01 = sIn[iyl0*IW + ixl1];
        float s10 = sIn[iyl1*IW + ixl0];
        float s11 = sIn[iyl1*IW + ixl1];
        #pragma unroll
        for (int j4 = 0; j4 < OCBt/4; j4++) {
            float4 w00 = *(const float4*)(sWt + k00*OCBt + j4*4);
            float4 w01 = *(const float4*)(sWt + k01*OCBt + j4*4);
            float4 w10 = *(const float4*)(sWt + k10*OCBt + j4*4);
            float4 w11 = *(const float4*)(sWt + k11*OCBt + j4*4);
            acc[j4*4+0] = fmaf(w00.x, s00, acc[j4*4+0]);
            acc[j4*4+1] = fmaf(w00.y, s00, acc[j4*4+1]);
            acc[j4*4+2] = fmaf(w00.z, s00, acc[j4*4+2]);
            acc[j4*4+3] = fmaf(w00.w, s00, acc[j4*4+3]);
            acc[j4*4+0] = fmaf(w01.x, s01, acc[j4*4+0]);
            acc[j4*4+1] = fmaf(w01.y, s01, acc[j4*4+1]);
            acc[j4*4+2] = fmaf(w01.z, s01, acc[j4*4+2]);
            acc[j4*4+3] = fmaf(w01.w, s01, acc[j4*4+3]);
            acc[j4*4+0] = fmaf(w10.x, s10, acc[j4*4+0]);
            acc[j4*4+1] = fmaf(w10.y, s10, acc[j4*4+1]);
            acc[j4*4+2] = fmaf(w10.z, s10, acc[j4*4+2]);
            acc[j4*4+3] = fmaf(w10.w, s10, acc[j4*4+3]);
            acc[j4*4+0] = fmaf(w11.x, s11, acc[j4*4+0]);
            acc[j4*4+1] = fmaf(w11.y, s11, acc[j4*4+1]);
            acc[j4*4+2] = fmaf(w11.z, s11, acc[j4*4+2]);
            acc[j4*4+3] = fmaf(w11.w, s11, acc[j4*4+3]);
        }
        __syncthreads();
    }

    #pragma unroll
    for (int o = 0; o < OCBt; o++) {
        int c = ocb + o;
        float v = acc[o];
        if (bias) v = __fadd_rn(v, __ldg(bias + c));
        if (act == 1)      v = (v > 0.f) ? v : __fmul_rn(0.01f, v);
        else if (act == 2) v = (v > 0.f) ? v : 0.f;
        out[(((size_t)n*Cout + c)*Hout + oy)*Wout + ox] = v;
    }
}

// ---------------- RVQ ----------------
// cnorm replicates XLA row-reduction semantics: squares rounded individually
// (mul then add, no fma), lane i + lane i+32, then shfl_down tree.
__global__ __launch_bounds__(256)
void cnorm_kernel(const float* __restrict__ cb, float* __restrict__ cn, int total)
{
    int warp = (blockIdx.x*256 + threadIdx.x) >> 5;
    int lane = threadIdx.x & 31;
    if (warp >= total) return;
    const float* p = cb + (size_t)warp*64;
    float a0 = p[lane], a1 = p[lane+32];
    float a = __fadd_rn(__fmul_rn(a0, a0), __fmul_rn(a1, a1));
    #pragma unroll
    for (int off = 16; off > 0; off >>= 1)
        a = __fadd_rn(a, __shfl_down_sync(0xffffffffu, a, off));
    if (lane == 0) cn[warp] = a;
}

// one thread per token; r/qacc in NCHW (feature d at stride HW).
// dot: single fp32 accumulator, ascending-d FFMA (cuBLAS sgemm order).
// dist = fl(fl(rn - 2*dot) + cn)  (2*dot exact; matches a-2b+c left-to-right).
__global__ __launch_bounds__(256)
void rvq_stage(float* __restrict__ r, float* __restrict__ qacc,
               const float* __restrict__ cb, const float* __restrict__ cnorm,
               float* __restrict__ idx_out, float* __restrict__ partials,
               int HW, int stage)
{
    __shared__ __align__(16) float sCt[64*32];   // [d][kk] 8KB
    __shared__ float sCn[32];
    __shared__ float sRed[256];

    const int t = blockIdx.x*256 + threadIdx.x;
    const int n = t / HW, p = t - n*HW;
    const size_t base = (size_t)n*64*HW + p;

    float rl[64];
    #pragma unroll
    for (int d = 0; d < 64; d++)
        rl[d] = r[base + (size_t)d*HW];
    float rn = 0.f;
    #pragma unroll
    for (int d = 0; d < 64; d++) rn = fmaf(rl[d], rl[d], rn);   // common offset: cannot affect argmin

    float best = 3.4e38f; int bidx = 0;
    for (int kb = 0; kb < 512; kb += 32) {
        __syncthreads();
        for (int i = threadIdx.x; i < 64*32; i += 256) {
            int kk = i & 31, d = i >> 5;
            sCt[i] = __ldg(cb + (size_t)(kb + kk)*64 + d);
        }
        if (threadIdx.x < 32) sCn[threadIdx.x] = cnorm[kb + threadIdx.x];
        __syncthreads();

        float dot[32];
        #pragma unroll
        for (int j = 0; j < 32; j++) dot[j] = 0.f;
        #pragma unroll
        for (int d = 0; d < 64; d++) {
            float rt = rl[d];
            const float4* cp = (const float4*)(sCt + d*32);
            #pragma unroll
            for (int j4 = 0; j4 < 8; j4++) {
                float4 c4 = cp[j4];
                dot[j4*4+0] = fmaf(rt, c4.x, dot[j4*4+0]);
                dot[j4*4+1] = fmaf(rt, c4.y, dot[j4*4+1]);
                dot[j4*4+2] = fmaf(rt, c4.z, dot[j4*4+2]);
                dot[j4*4+3] = fmaf(rt, c4.w, dot[j4*4+3]);
            }
        }
        #pragma unroll
        for (int j = 0; j < 32; j++) {
            float dist = __fadd_rn(__fadd_rn(rn, -__fmul_rn(2.f, dot[j])), sCn[j]);
            if (dist < best) { best = dist; bidx = kb + j; }   // strict <: first-min, matches argmin
        }
    }

    float lsum = 0.f;
    const float* cq = cb + (size_t)bidx*64;
    #pragma unroll
    for (int d = 0; d < 64; d++) {
        float q = __ldg(cq + d);
        float diff = __fadd_rn(q, -rl[d]);
        lsum = fmaf(diff, diff, lsum);
        // straight-through value: fl(r + fl(q - r))  (one extra rounding vs q)
        float q_st = __fadd_rn(rl[d], diff);
        size_t ii = base + (size_t)d*HW;
        if (stage == 0) qacc[ii] = q_st;
        else            qacc[ii] = __fadd_rn(qacc[ii], q_st);
        r[ii] = __fadd_rn(rl[d], -q);
    }
    idx_out[(size_t)t*4 + stage] = (float)bidx;

    sRed[threadIdx.x] = lsum;
    __syncthreads();
    for (int sft = 128; sft > 0; sft >>= 1) {
        if (threadIdx.x < sft) sRed[threadIdx.x] += sRed[threadIdx.x + sft];
        __syncthreads();
    }
    if (threadIdx.x == 0) partials[stage*256 + blockIdx.x] = sRed[0];
}

__global__ __launch_bounds__(256)
void loss_finalize(const float* __restrict__ partials, float* __restrict__ loss_out, float scale)
{
    __shared__ float sRed[256];
    int stage = blockIdx.x;
    sRed[threadIdx.x] = partials[stage*256 + threadIdx.x];
    __syncthreads();
    for (int sft = 128; sft > 0; sft >>= 1) {
        if (threadIdx.x < sft) sRed[threadIdx.x] += sRed[threadIdx.x + sft];
        __syncthreads();
    }
    if (threadIdx.x == 0) loss_out[stage] = 0.25f * (sRed[0] * scale);  // scale = 2^-22, exact
}

// ---------------- launch ----------------
extern "C" void kernel_launch(void* const* d_in, const int* in_sizes, int n_in,
                              void* d_out, int out_size)
{
    const float* x     = (const float*)d_in[0];
    const float* e1w   = (const float*)d_in[1];
    const float* e1b   = (const float*)d_in[2];
    const float* e2w   = (const float*)d_in[3];
    const float* e2b   = (const float*)d_in[4];
    const float* e3w   = (const float*)d_in[5];
    const float* e3b   = (const float*)d_in[6];
    const float* r1aw  = (const float*)d_in[7];
    const float* r1bw  = (const float*)d_in[8];
    const float* r2aw  = (const float*)d_in[9];
    const float* r2bw  = (const float*)d_in[10];
    const float* e4w   = (const float*)d_in[11];
    const float* e4b   = (const float*)d_in[12];
    const float* cbs   = (const float*)d_in[13];
    const float* d1w   = (const float*)d_in[14];
    const float* d1b   = (const float*)d_in[15];
    const float* dr1aw = (const float*)d_in[16];
    const float* dr1bw = (const float*)d_in[17];
    const float* dr2aw = (const float*)d_in[18];
    const float* dr2bw = (const float*)d_in[19];
    const float* dt1w  = (const float*)d_in[20];
    const float* dt1b  = (const float*)d_in[21];
    const float* dt2w  = (const float*)d_in[22];
    const float* dt2b  = (const float*)d_in[23];

    float* out = (float*)d_out;
    float* recons  = out;                        // 16*4*256*256
    float* idxout  = out + (size_t)16*4*256*256; // 16*64*64*4
    float* lossout = idxout + (size_t)16*64*64*4;// 4

    float *A,*B,*C,*D,*R,*Q,*CN,*P;
    cudaGetSymbolAddress((void**)&A,  g_bufA);
    cudaGetSymbolAddress((void**)&B,  g_bufB);
    cudaGetSymbolAddress((void**)&C,  g_bufC);
    cudaGetSymbolAddress((void**)&D,  g_bufD);
    cudaGetSymbolAddress((void**)&R,  g_r);
    cudaGetSymbolAddress((void**)&Q,  g_q);
    cudaGetSymbolAddress((void**)&CN, g_cnorm);
    cudaGetSymbolAddress((void**)&P,  g_partials);

    // codebook norms (all 4 stages): one warp per code
    cnorm_kernel<<<256, 256>>>(cbs, CN, 4*512);

    // ---- encoder ----
    conv_tiled<4,2><<<dim3(8,8,16*4), 256>>>(x, e1w, e1b, nullptr, A,
                                             16,4,256,256, 64,128,128, 1, 1);
    conv_tiled<4,2><<<dim3(4,4,16*8), 256>>>(A, e2w, e2b, nullptr, B,
                                             16,64,128,128, 128,64,64, 1, 1);
    conv_tiled<3,1><<<dim3(4,4,16*8), 256>>>(B, e3w, e3b, nullptr, C,
                                             16,128,64,64, 128,64,64, 1, 1);
    conv_tiled<3,1><<<dim3(4,4,16*8), 256>>>(C, r1aw, nullptr, nullptr, D,
                                             16,128,64,64, 128,64,64, 1, 2);
    conv_tiled<1,1><<<dim3(4,4,16*8), 256>>>(D, r1bw, nullptr, C, B,
                                             16,128,64,64, 128,64,64, 0, 0);
    conv_tiled<3,1><<<dim3(4,4,16*8), 256>>>(B, r2aw, nullptr, nullptr, D,
                                             16,128,64,64, 128,64,64, 1, 2);
    conv_tiled<1,1><<<dim3(4,4,16*8), 256>>>(D, r2bw, nullptr, B, C,
                                             16,128,64,64, 128,64,64, 0, 1);
    conv_tiled<1,1><<<dim3(4,4,16*4), 256>>>(C, e4w, e4b, nullptr, R,
                                             16,128,64,64, 64,64,64, 0, 1);

    // ---- residual VQ: 4 stages ----
    for (int s = 0; s < 4; s++)
        rvq_stage<<<256, 256>>>(R, Q, cbs + (size_t)s*512*64, CN + s*512,
                                idxout, P, 64*64, s);
    loss_finalize<<<4, 256>>>(P, lossout, 1.f/(65536.f*64.f));

    // ---- decoder ----
    conv_tiled<3,1><<<dim3(4,4,16*8), 256>>>(Q, d1w, d1b, nullptr, B,
                                             16,64,64,64, 128,64,64, 1, 1);
    conv_tiled<3,1><<<dim3(4,4,16*8), 256>>>(B, dr1aw, nullptr, nullptr, D,
                                             16,128,64,64, 128,64,64, 1, 2);
    conv_tiled<1,1><<<dim3(4,4,16*8), 256>>>(D, dr1bw, nullptr, B, C,
                                             16,128,64,64, 128,64,64, 0, 0);
    conv_tiled<3,1><<<dim3(4,4,16*8), 256>>>(C, dr2aw, nullptr, nullptr, D,
                                             16,128,64,64, 128,64,64, 1, 2);
    conv_tiled<1,1><<<dim3(4,4,16*8), 256>>>(D, dr2bw, nullptr, C, B,
                                             16,128,64,64, 128,64,64, 0, 1);
    convT_tiled<16><<<dim3(8,8,16*4), 256>>>(B, dt1w, dt1b, A,
                                             16,128,64,64, 64, 1);
    convT_tiled<4><<<dim3(16,16,16*1), 256>>>(A, dt2w, dt2b, recons,
                                              16,64,128,128, 4, 2);
}

// round 4
// speedup vs baseline: 1.0387x; 1.0387x over previous
#include <cuda_runtime.h>
#include <cuda_bf16.h>
#include <cstddef>

// ---------------- scratch (device globals; no allocation allowed) ----------------
__device__ float g_bufA[16u*64u*128u*128u];   // 16.78M floats (e1 out / dt1 out)
__device__ float g_bufB[16u*128u*64u*64u];    // 8.39M
__device__ float g_bufC[16u*128u*64u*64u];
__device__ float g_bufD[16u*128u*64u*64u];
__device__ float g_r  [16u*64u*64u*64u];      // residual tokens (NCHW view)
__device__ float g_q  [16u*64u*64u*64u];      // quantized accumulation (NCHW view)
__device__ float g_cnorm[4*512];
__device__ float g_partials[4*256];

// ---------------- register-tiled direct convolution ----------------
// Block: 256 threads -> 32x32 output tile x 16 output channels.
// Each thread: 2x2 spatial outputs x 16 oc = 64 accumulators.
// Per-output accumulation order: ci asc, then (ky,kx) asc, single FFMA chain
// (bit-identical to the round-3 passing kernel -> numerics locked).
// act: 0=none, 1=leaky_relu(0.01), 2=relu.  bias/resid may be nullptr.
template<int K, int S>
__global__ __launch_bounds__(256, 2)
void conv_rt(const float* __restrict__ in, const float* __restrict__ wt,
             const float* __restrict__ bias, const float* __restrict__ resid,
             float* __restrict__ out,
             int N, int Cin, int Hin, int Win, int Cout, int Hout, int Wout,
             int pad, int act)
{
    constexpr int IW  = 32*S + K - S;
    constexpr int IWP = (IW & 1) ? IW : IW + 1;   // odd row stride: kill bank conflicts
    __shared__ float sIn[IW * IWP];
    __shared__ __align__(16) float sWt[K*K*16];   // [tap][oc]

    const int chunks = Cout >> 4;
    const int n   = blockIdx.z / chunks;
    const int ocb = (blockIdx.z - n*chunks) << 4;
    const int ox0 = blockIdx.x << 5, oy0 = blockIdx.y << 5;
    const int tx = threadIdx.x & 15, ty = threadIdx.x >> 4;
    const int ix0 = ox0*S - pad, iy0 = oy0*S - pad;

    float acc[16][2][2];
    #pragma unroll
    for (int o = 0; o < 16; o++) {
        acc[o][0][0] = 0.f; acc[o][0][1] = 0.f;
        acc[o][1][0] = 0.f; acc[o][1][1] = 0.f;
    }

    for (int ci = 0; ci < Cin; ci++) {
        const float* ip = in + ((size_t)(n*Cin + ci)*Hin)*Win;
        for (int i = threadIdx.x; i < IW*IW; i += 256) {
            int r = i / IW, c = i - r*IW;
            int gy = iy0 + r, gx = ix0 + c;
            float v = 0.f;
            if ((unsigned)gy < (unsigned)Hin && (unsigned)gx < (unsigned)Win)
                v = __ldg(ip + (size_t)gy*Win + gx);
            sIn[r*IWP + c] = v;
        }
        for (int i = threadIdx.x; i < K*K*16; i += 256) {
            int oc = i & 15, kk = i >> 4;
            sWt[i] = __ldg(wt + ((size_t)(ocb+oc)*Cin + ci)*(K*K) + kk);
        }
        __syncthreads();

        if constexpr (S == 1) {
            float inr[K+1][K+1];
            #pragma unroll
            for (int r = 0; r < K+1; r++)
                #pragma unroll
                for (int c = 0; c < K+1; c++)
                    inr[r][c] = sIn[(ty*2 + r)*IWP + tx*2 + c];
            #pragma unroll
            for (int ky = 0; ky < K; ky++)
            #pragma unroll
            for (int kx = 0; kx < K; kx++) {
                const float4* wp = (const float4*)(sWt + (ky*K + kx)*16);
                float w[16];
                *(float4*)&w[0]  = wp[0];
                *(float4*)&w[4]  = wp[1];
                *(float4*)&w[8]  = wp[2];
                *(float4*)&w[12] = wp[3];
                #pragma unroll
                for (int dy = 0; dy < 2; dy++)
                #pragma unroll
                for (int dx = 0; dx < 2; dx++) {
                    float s = inr[ky+dy][kx+dx];
                    #pragma unroll
                    for (int o = 0; o < 16; o++)
                        acc[o][dy][dx] = fmaf(w[o], s, acc[o][dy][dx]);
                }
            }
        } else {
            #pragma unroll
            for (int ky = 0; ky < K; ky++)
            #pragma unroll
            for (int kx = 0; kx < K; kx++) {
                const float4* wp = (const float4*)(sWt + (ky*K + kx)*16);
                float w[16];
                *(float4*)&w[0]  = wp[0];
                *(float4*)&w[4]  = wp[1];
                *(float4*)&w[8]  = wp[2];
                *(float4*)&w[12] = wp[3];
                #pragma unroll
                for (int dy = 0; dy < 2; dy++)
                #pragma unroll
                for (int dx = 0; dx < 2; dx++) {
                    float s = sIn[((ty*2+dy)*S + ky)*IWP + (tx*2+dx)*S + kx];
                    #pragma unroll
                    for (int o = 0; o < 16; o++)
                        acc[o][dy][dx] = fmaf(w[o], s, acc[o][dy][dx]);
                }
            }
        }
        __syncthreads();
    }

    const int oy = oy0 + ty*2, ox = ox0 + tx*2;
    #pragma unroll
    for (int o = 0; o < 16; o++) {
        int c = ocb + o;
        float bv = bias ? __ldg(bias + c) : 0.f;
        #pragma unroll
        for (int dy = 0; dy < 2; dy++)
        #pragma unroll
        for (int dx = 0; dx < 2; dx++) {
            float v = acc[o][dy][dx];
            if (bias)  v = __fadd_rn(v, bv);
            size_t oi = (((size_t)n*Cout + c)*Hout + (oy+dy))*Wout + (ox+dx);
            if (resid) v = __fadd_rn(v, resid[oi]);
            if (act == 1)      v = (v > 0.f) ? v : __fmul_rn(0.01f, v);
            else if (act == 2) v = (v > 0.f) ? v : 0.f;
            out[oi] = v;
        }
    }
}

// ---------------- register-tiled transposed conv (k=4,s=2,p=1), torch layout (in,out,4,4) ----
// Block: 32x32 output tile; thread handles 4 SAME-PARITY outputs
// (oy0+ty, ox0+tx) + offsets {0,16}x{0,16}, so the 4 parity taps' weights are
// reused across all 4 outputs. Tap order per output: (ky asc, kx asc) ==
// round-3 order (k00,k01,k10,k11) -> bit-identical accumulation.
template<int OCBt, int LOG_OCB>
__global__ __launch_bounds__(256, 2)
void convT_rt(const float* __restrict__ in, const float* __restrict__ wt,
              const float* __restrict__ bias, float* __restrict__ out,
              int N, int Cin, int Hin, int Win, int Cout, int act)
{
    constexpr int IW = 18, IWP = 19;
    __shared__ float sIn[IW*IWP];
    __shared__ __align__(16) float sWt[16*OCBt];   // [tap][oc]

    const int Hout = Hin*2, Wout = Win*2;
    const int chunks = Cout >> LOG_OCB;
    const int n   = blockIdx.z / chunks;
    const int ocb = (blockIdx.z - n*chunks) << LOG_OCB;
    const int ox0 = blockIdx.x << 5, oy0 = blockIdx.y << 5;
    const int tx = threadIdx.x & 15, ty = threadIdx.x >> 4;
    const int iyb = (oy0 >> 1) - 1, ixb = (ox0 >> 1) - 1;

    const int ky0 = 1 - (ty & 1), kx0 = 1 - (tx & 1);
    const int hy = (ty >> 1) + 1 + (ty & 1);   // local row for tap ky0 (output row ty)
    const int hx = (tx >> 1) + 1 + (tx & 1);

    float acc[OCBt][2][2];
    #pragma unroll
    for (int o = 0; o < OCBt; o++) {
        acc[o][0][0] = 0.f; acc[o][0][1] = 0.f;
        acc[o][1][0] = 0.f; acc[o][1][1] = 0.f;
    }

    for (int ci = 0; ci < Cin; ci++) {
        const float* ip = in + ((size_t)(n*Cin + ci)*Hin)*Win;
        for (int i = threadIdx.x; i < IW*IW; i += 256) {
            int r = i / IW, c = i - r*IW;
            int gy = iyb + r, gx = ixb + c;
            float v = 0.f;
            if ((unsigned)gy < (unsigned)Hin && (unsigned)gx < (unsigned)Win)
                v = __ldg(ip + (size_t)gy*Win + gx);
            sIn[r*IWP + c] = v;
        }
        for (int i = threadIdx.x; i < 16*OCBt; i += 256) {
            int oc = i & (OCBt-1), kk = i >> LOG_OCB;
            sWt[i] = __ldg(wt + ((size_t)ci*Cout + (ocb+oc))*16 + kk);
        }
        __syncthreads();

        float vin[2][2][2][2];   // [ey][tap_y][ex][tap_x]
        #pragma unroll
        for (int ey = 0; ey < 2; ey++)
        #pragma unroll
        for (int tyt = 0; tyt < 2; tyt++)
        #pragma unroll
        for (int ex = 0; ex < 2; ex++)
        #pragma unroll
        for (int txt = 0; txt < 2; txt++)
            vin[ey][tyt][ex][txt] = sIn[(hy + 8*ey - tyt)*IWP + (hx + 8*ex - txt)];

        #pragma unroll
        for (int tyt = 0; tyt < 2; tyt++)
        #pragma unroll
        for (int txt = 0; txt < 2; txt++) {
            const int kk = (ky0 + 2*tyt)*4 + (kx0 + 2*txt);
            const float4* wp = (const float4*)(sWt + kk*OCBt);
            float w[OCBt];
            #pragma unroll
            for (int j4 = 0; j4 < OCBt/4; j4++)
                *(float4*)&w[j4*4] = wp[j4];
            #pragma unroll
            for (int ey = 0; ey < 2; ey++)
            #pragma unroll
            for (int ex = 0; ex < 2; ex++) {
                float s = vin[ey][tyt][ex][txt];
                #pragma unroll
                for (int o = 0; o < OCBt; o++)
                    acc[o][ey][ex] = fmaf(w[o], s, acc[o][ey][ex]);
            }
        }
        __syncthreads();
    }

    #pragma unroll
    for (int o = 0; o < OCBt; o++) {
        int c = ocb + o;
        float bv = bias ? __ldg(bias + c) : 0.f;
        #pragma unroll
        for (int ey = 0; ey < 2; ey++)
        #pragma unroll
        for (int ex = 0; ex < 2; ex++) {
            float v = acc[o][ey][ex];
            if (bias) v = __fadd_rn(v, bv);
            int oy = oy0 + ty + 16*ey, ox = ox0 + tx + 16*ex;
            if (act == 1)      v = (v > 0.f) ? v : __fmul_rn(0.01f, v);
            else if (act == 2) v = (v > 0.f) ? v : 0.f;
            out[(((size_t)n*Cout + c)*Hout + oy)*Wout + ox] = v;
        }
    }
}

// ---------------- RVQ (numerics locked: do not touch) ----------------
__global__ __launch_bounds__(256)
void cnorm_kernel(const float* __restrict__ cb, float* __restrict__ cn, int total)
{
    int warp = (blockIdx.x*256 + threadIdx.x) >> 5;
    int lane = threadIdx.x & 31;
    if (warp >= total) return;
    const float* p = cb + (size_t)warp*64;
    float a0 = p[lane], a1 = p[lane+32];
    float a = __fadd_rn(__fmul_rn(a0, a0), __fmul_rn(a1, a1));
    #pragma unroll
    for (int off = 16; off > 0; off >>= 1)
        a = __fadd_rn(a, __shfl_down_sync(0xffffffffu, a, off));
    if (lane == 0) cn[warp] = a;
}

__global__ __launch_bounds__(256)
void rvq_stage(float* __restrict__ r, float* __restrict__ qacc,
               const float* __restrict__ cb, const float* __restrict__ cnorm,
               float* __restrict__ idx_out, float* __restrict__ partials,
               int HW, int stage)
{
    __shared__ __align__(16) float sCt[64*32];   // [d][kk] 8KB
    __shared__ float sCn[32];
    __shared__ float sRed[256];

    const int t = blockIdx.x*256 + threadIdx.x;
    const int n = t / HW, p = t - n*HW;
    const size_t base = (size_t)n*64*HW + p;

    float rl[64];
    #pragma unroll
    for (int d = 0; d < 64; d++)
        rl[d] = r[base + (size_t)d*HW];
    float rn = 0.f;
    #pragma unroll
    for (int d = 0; d < 64; d++) rn = fmaf(rl[d], rl[d], rn);

    float best = 3.4e38f; int bidx = 0;
    for (int kb = 0; kb < 512; kb += 32) {
        __syncthreads();
        for (int i = threadIdx.x; i < 64*32; i += 256) {
            int kk = i & 31, d = i >> 5;
            sCt[i] = __ldg(cb + (size_t)(kb + kk)*64 + d);
        }
        if (threadIdx.x < 32) sCn[threadIdx.x] = cnorm[kb + threadIdx.x];
        __syncthreads();

        float dot[32];
        #pragma unroll
        for (int j = 0; j < 32; j++) dot[j] = 0.f;
        #pragma unroll
        for (int d = 0; d < 64; d++) {
            float rt = rl[d];
            const float4* cp = (const float4*)(sCt + d*32);
            #pragma unroll
            for (int j4 = 0; j4 < 8; j4++) {
                float4 c4 = cp[j4];
                dot[j4*4+0] = fmaf(rt, c4.x, dot[j4*4+0]);
                dot[j4*4+1] = fmaf(rt, c4.y, dot[j4*4+1]);
                dot[j4*4+2] = fmaf(rt, c4.z, dot[j4*4+2]);
                dot[j4*4+3] = fmaf(rt, c4.w, dot[j4*4+3]);
            }
        }
        #pragma unroll
        for (int j = 0; j < 32; j++) {
            float dist = __fadd_rn(__fadd_rn(rn, -__fmul_rn(2.f, dot[j])), sCn[j]);
            if (dist < best) { best = dist; bidx = kb + j; }
        }
    }

    float lsum = 0.f;
    const float* cq = cb + (size_t)bidx*64;
    #pragma unroll
    for (int d = 0; d < 64; d++) {
        float q = __ldg(cq + d);
        float diff = __fadd_rn(q, -rl[d]);
        lsum = fmaf(diff, diff, lsum);
        float q_st = __fadd_rn(rl[d], diff);
        size_t ii = base + (size_t)d*HW;
        if (stage == 0) qacc[ii] = q_st;
        else            qacc[ii] = __fadd_rn(qacc[ii], q_st);
        r[ii] = __fadd_rn(rl[d], -q);
    }
    idx_out[(size_t)t*4 + stage] = (float)bidx;

    sRed[threadIdx.x] = lsum;
    __syncthreads();
    for (int sft = 128; sft > 0; sft >>= 1) {
        if (threadIdx.x < sft) sRed[threadIdx.x] += sRed[threadIdx.x + sft];
        __syncthreads();
    }
    if (threadIdx.x == 0) partials[stage*256 + blockIdx.x] = sRed[0];
}

__global__ __launch_bounds__(256)
void loss_finalize(const float* __restrict__ partials, float* __restrict__ loss_out, float scale)
{
    __shared__ float sRed[256];
    int stage = blockIdx.x;
    sRed[threadIdx.x] = partials[stage*256 + threadIdx.x];
    __syncthreads();
    for (int sft = 128; sft > 0; sft >>= 1) {
        if (threadIdx.x < sft) sRed[threadIdx.x] += sRed[threadIdx.x + sft];
        __syncthreads();
    }
    if (threadIdx.x == 0) loss_out[stage] = 0.25f * (sRed[0] * scale);
}

// ---------------- launch ----------------
extern "C" void kernel_launch(void* const* d_in, const int* in_sizes, int n_in,
                              void* d_out, int out_size)
{
    const float* x     = (const float*)d_in[0];
    const float* e1w   = (const float*)d_in[1];
    const float* e1b   = (const float*)d_in[2];
    const float* e2w   = (const float*)d_in[3];
    const float* e2b   = (const float*)d_in[4];
    const float* e3w   = (const float*)d_in[5];
    const float* e3b   = (const float*)d_in[6];
    const float* r1aw  = (const float*)d_in[7];
    const float* r1bw  = (const float*)d_in[8];
    const float* r2aw  = (const float*)d_in[9];
    const float* r2bw  = (const float*)d_in[10];
    const float* e4w   = (const float*)d_in[11];
    const float* e4b   = (const float*)d_in[12];
    const float* cbs   = (const float*)d_in[13];
    const float* d1w   = (const float*)d_in[14];
    const float* d1b   = (const float*)d_in[15];
    const float* dr1aw = (const float*)d_in[16];
    const float* dr1bw = (const float*)d_in[17];
    const float* dr2aw = (const float*)d_in[18];
    const float* dr2bw = (const float*)d_in[19];
    const float* dt1w  = (const float*)d_in[20];
    const float* dt1b  = (const float*)d_in[21];
    const float* dt2w  = (const float*)d_in[22];
    const float* dt2b  = (const float*)d_in[23];

    float* out = (float*)d_out;
    float* recons  = out;                        // 16*4*256*256
    float* idxout  = out + (size_t)16*4*256*256; // 16*64*64*4
    float* lossout = idxout + (size_t)16*64*64*4;// 4

    float *A,*B,*C,*D,*R,*Q,*CN,*P;
    cudaGetSymbolAddress((void**)&A,  g_bufA);
    cudaGetSymbolAddress((void**)&B,  g_bufB);
    cudaGetSymbolAddress((void**)&C,  g_bufC);
    cudaGetSymbolAddress((void**)&D,  g_bufD);
    cudaGetSymbolAddress((void**)&R,  g_r);
    cudaGetSymbolAddress((void**)&Q,  g_q);
    cudaGetSymbolAddress((void**)&CN, g_cnorm);
    cudaGetSymbolAddress((void**)&P,  g_partials);

    cnorm_kernel<<<256, 256>>>(cbs, CN, 4*512);

    // ---- encoder ----
    conv_rt<4,2><<<dim3(4,4,64), 256>>>(x, e1w, e1b, nullptr, A,
                                        16,4,256,256, 64,128,128, 1, 1);
    conv_rt<4,2><<<dim3(2,2,128), 256>>>(A, e2w, e2b, nullptr, B,
                                         16,64,128,128, 128,64,64, 1, 1);
    conv_rt<3,1><<<dim3(2,2,128), 256>>>(B, e3w, e3b, nullptr, C,
                                         16,128,64,64, 128,64,64, 1, 1);
    conv_rt<3,1><<<dim3(2,2,128), 256>>>(C, r1aw, nullptr, nullptr, D,
                                         16,128,64,64, 128,64,64, 1, 2);
    conv_rt<1,1><<<dim3(2,2,128), 256>>>(D, r1bw, nullptr, C, B,
                                         16,128,64,64, 128,64,64, 0, 0);
    conv_rt<3,1><<<dim3(2,2,128), 256>>>(B, r2aw, nullptr, nullptr, D,
                                         16,128,64,64, 128,64,64, 1, 2);
    conv_rt<1,1><<<dim3(2,2,128), 256>>>(D, r2bw, nullptr, B, C,
                                         16,128,64,64, 128,64,64, 0, 1);
    conv_rt<1,1><<<dim3(2,2,64), 256>>>(C, e4w, e4b, nullptr, R,
                                        16,128,64,64, 64,64,64, 0, 1);

    // ---- residual VQ: 4 stages ----
    for (int s = 0; s < 4; s++)
        rvq_stage<<<256, 256>>>(R, Q, cbs + (size_t)s*512*64, CN + s*512,
                                idxout, P, 64*64, s);
    loss_finalize<<<4, 256>>>(P, lossout, 1.f/(65536.f*64.f));

    // ---- decoder ----
    conv_rt<3,1><<<dim3(2,2,128), 256>>>(Q, d1w, d1b, nullptr, B,
                                         16,64,64,64, 128,64,64, 1, 1);
    conv_rt<3,1><<<dim3(2,2,128), 256>>>(B, dr1aw, nullptr, nullptr, D,
                                         16,128,64,64, 128,64,64, 1, 2);
    conv_rt<1,1><<<dim3(2,2,128), 256>>>(D, dr1bw, nullptr, B, C,
                                         16,128,64,64, 128,64,64, 0, 0);
    conv_rt<3,1><<<dim3(2,2,128), 256>>>(C, dr2aw, nullptr, nullptr, D,
                                         16,128,64,64, 128,64,64, 1, 2);
    conv_rt<1,1><<<dim3(2,2,128), 256>>>(D, dr2bw, nullptr, C, B,
                                         16,128,64,64, 128,64,64, 0, 1);
    convT_rt<16,4><<<dim3(4,4,64), 256>>>(B, dt1w, dt1b, A,
                                          16,128,64,64, 64, 1);
    convT_rt<4,2><<<dim3(8,8,16), 256>>>(A, dt2w, dt2b, recons,
                                         16,64,128,128, 4, 2);
}

// round 5
// speedup vs baseline: 1.3343x; 1.2846x over previous
#include <cuda_runtime.h>
#include <cuda_bf16.h>
#include <cstddef>
#include <cstdint>

// ---------------- scratch (device globals; no allocation allowed) ----------------
__device__ float g_bufA[16u*64u*128u*128u];   // 16.78M floats (e1 out / dt1 out)
__device__ float g_bufB[16u*128u*64u*64u];    // 8.39M
__device__ float g_bufC[16u*128u*64u*64u];
__device__ float g_bufD[16u*128u*64u*64u];
__device__ float g_r  [16u*64u*64u*64u];      // residual tokens (NCHW view)
__device__ float g_q  [16u*64u*64u*64u];      // quantized accumulation (NCHW view)
__device__ float g_cnorm[4*512];
__device__ float g_partials[4*256];

// ---------------- cp.async helpers ----------------
__device__ __forceinline__ void cp4(void* smem_dst, const void* gsrc, bool pred) {
    uint32_t s = (uint32_t)__cvta_generic_to_shared(smem_dst);
    int sz = pred ? 4 : 0;               // src-size 0 -> zero-fill (free OOB padding)
    asm volatile("cp.async.ca.shared.global [%0], [%1], 4, %2;" :: "r"(s), "l"(gsrc), "r"(sz));
}
__device__ __forceinline__ void cp_commit() {
    asm volatile("cp.async.commit_group;");
}
template<int Nw>
__device__ __forceinline__ void cp_wait() {
    asm volatile("cp.async.wait_group %0;" :: "n"(Nw));
}

// ---------------- pipelined register-tiled direct convolution ----------------
// Block: 256 threads -> 32x32 output tile x 16 output channels.
// Each thread: 2x2 spatial outputs x 16 oc = 64 accumulators.
// CIB input channels staged per barrier, double-buffered via cp.async.
// Per-output accumulation: ci asc, (ky,kx) asc, single FFMA chain — bit-identical
// to the round-3/4 passing kernels. NUMERICS LOCKED.
// act: 0=none, 1=leaky_relu(0.01), 2=relu.  bias/resid may be nullptr.
template<int K, int S, int CIB>
__global__ __launch_bounds__(256, 2)
void conv_pipe(const float* __restrict__ in, const float* __restrict__ wt,
               const float* __restrict__ bias, const float* __restrict__ resid,
               float* __restrict__ out,
               int N, int Cin, int Hin, int Win, int Cout, int Hout, int Wout,
               int pad, int act)
{
    constexpr int IW  = 32*S + K - S;
    constexpr int IWP = IW | 1;          // odd row stride: no bank conflicts
    constexpr int KK  = K*K;
    __shared__ float sIn[2][CIB*IW*IWP];
    __shared__ __align__(16) float sWt[2][CIB*KK*16];   // [cl][tap][oc]

    const int tid = threadIdx.x;
    const int chunks = Cout >> 4;
    const int n   = blockIdx.z / chunks;
    const int ocb = (blockIdx.z - n*chunks) << 4;
    const int ox0 = blockIdx.x << 5, oy0 = blockIdx.y << 5;
    const int tx = tid & 15, ty = tid >> 4;
    const int ix0 = ox0*S - pad, iy0 = oy0*S - pad;
    const int HWin = Hin*Win;
    const float* inb = in + (size_t)n*Cin*HWin;
    const int tx2 = tid & 31, ty2 = tid >> 5;

    auto load_stage = [&](int cib, int buf) {
        #pragma unroll
        for (int cl = 0; cl < CIB; cl++) {
            const float* ip = inb + (size_t)(cib + cl)*HWin;
            float* sp = &sIn[buf][cl*IW*IWP];
            for (int r = ty2; r < IW; r += 8) {
                int gy = iy0 + r;
                bool rowok = (unsigned)gy < (unsigned)Hin;
                const float* rp = ip + (size_t)gy*Win;
                for (int c = tx2; c < IW; c += 32) {
                    int gx = ix0 + c;
                    cp4(sp + r*IWP + c, rp + gx,
                        rowok && ((unsigned)gx < (unsigned)Win));
                }
            }
        }
        for (int i = tid; i < CIB*KK*16; i += 256) {
            int oc = i & 15;
            int rest = i >> 4;
            int kk = rest % KK, cl = rest / KK;
            cp4(&sWt[buf][i], wt + ((size_t)(ocb+oc)*Cin + (cib+cl))*KK + kk, true);
        }
    };

    float acc[16][2][2];
    #pragma unroll
    for (int o = 0; o < 16; o++) {
        acc[o][0][0] = 0.f; acc[o][0][1] = 0.f;
        acc[o][1][0] = 0.f; acc[o][1][1] = 0.f;
    }

    const int NB = Cin / CIB;
    load_stage(0, 0);
    cp_commit();

    for (int b = 0; b < NB; b++) {
        const int buf = b & 1;
        if (b + 1 < NB) {
            load_stage((b+1)*CIB, buf ^ 1);
            cp_commit();
            cp_wait<1>();
        } else {
            cp_wait<0>();
        }
        __syncthreads();

        #pragma unroll
        for (int cl = 0; cl < CIB; cl++) {
            const float* sI = &sIn[buf][cl*IW*IWP];
            const float* sW = &sWt[buf][cl*KK*16];
            if constexpr (S == 1) {
                float inr[K+1][K+1];
                #pragma unroll
                for (int r = 0; r < K+1; r++)
                    #pragma unroll
                    for (int c = 0; c < K+1; c++)
                        inr[r][c] = sI[(ty*2 + r)*IWP + tx*2 + c];
                #pragma unroll
                for (int ky = 0; ky < K; ky++)
                #pragma unroll
                for (int kx = 0; kx < K; kx++) {
                    const float4* wp = (const float4*)(sW + (ky*K + kx)*16);
                    float w[16];
                    *(float4*)&w[0]  = wp[0];
                    *(float4*)&w[4]  = wp[1];
                    *(float4*)&w[8]  = wp[2];
                    *(float4*)&w[12] = wp[3];
                    #pragma unroll
                    for (int dy = 0; dy < 2; dy++)
                    #pragma unroll
                    for (int dx = 0; dx < 2; dx++) {
                        float s = inr[ky+dy][kx+dx];
                        #pragma unroll
                        for (int o = 0; o < 16; o++)
                            acc[o][dy][dx] = fmaf(w[o], s, acc[o][dy][dx]);
                    }
                }
            } else {
                #pragma unroll
                for (int ky = 0; ky < K; ky++)
                #pragma unroll
                for (int kx = 0; kx < K; kx++) {
                    const float4* wp = (const float4*)(sW + (ky*K + kx)*16);
                    float w[16];
                    *(float4*)&w[0]  = wp[0];
                    *(float4*)&w[4]  = wp[1];
                    *(float4*)&w[8]  = wp[2];
                    *(float4*)&w[12] = wp[3];
                    #pragma unroll
                    for (int dy = 0; dy < 2; dy++)
                    #pragma unroll
                    for (int dx = 0; dx < 2; dx++) {
                        float s = sI[((ty*2+dy)*S + ky)*IWP + (tx*2+dx)*S + kx];
                        #pragma unroll
                        for (int o = 0; o < 16; o++)
                            acc[o][dy][dx] = fmaf(w[o], s, acc[o][dy][dx]);
                    }
                }
            }
        }
        __syncthreads();
    }

    const int oy = oy0 + ty*2, ox = ox0 + tx*2;
    #pragma unroll
    for (int o = 0; o < 16; o++) {
        int c = ocb + o;
        float bv = bias ? __ldg(bias + c) : 0.f;
        #pragma unroll
        for (int dy = 0; dy < 2; dy++)
        #pragma unroll
        for (int dx = 0; dx < 2; dx++) {
            float v = acc[o][dy][dx];
            if (bias)  v = __fadd_rn(v, bv);
            size_t oi = (((size_t)n*Cout + c)*Hout + (oy+dy))*Wout + (ox+dx);
            if (resid) v = __fadd_rn(v, resid[oi]);
            if (act == 1)      v = (v > 0.f) ? v : __fmul_rn(0.01f, v);
            else if (act == 2) v = (v > 0.f) ? v : 0.f;
            out[oi] = v;
        }
    }
}

// ---------------- pipelined transposed conv (k=4,s=2,p=1), torch layout (in,out,4,4) ----
// 32x32 output tile; thread handles 4 same-parity outputs ({0,16}x{0,16} offsets).
// Tap order per output (ky asc, kx asc) == previous passing kernels. NUMERICS LOCKED.
template<int OCBt, int LOG_OCB, int CIB>
__global__ __launch_bounds__(256, 2)
void convT_pipe(const float* __restrict__ in, const float* __restrict__ wt,
                const float* __restrict__ bias, float* __restrict__ out,
                int N, int Cin, int Hin, int Win, int Cout, int act)
{
    constexpr int IW = 18, IWP = 19;
    __shared__ float sIn[2][CIB*IW*IWP];
    __shared__ __align__(16) float sWt[2][CIB*16*OCBt];   // [cl][tap][oc]

    const int tid = threadIdx.x;
    const int Hout = Hin*2, Wout = Win*2;
    const int chunks = Cout >> LOG_OCB;
    const int n   = blockIdx.z / chunks;
    const int ocb = (blockIdx.z - n*chunks) << LOG_OCB;
    const int ox0 = blockIdx.x << 5, oy0 = blockIdx.y << 5;
    const int tx = tid & 15, ty = tid >> 4;
    const int iyb = (oy0 >> 1) - 1, ixb = (ox0 >> 1) - 1;
    const int HWin = Hin*Win;
    const float* inb = in + (size_t)n*Cin*HWin;
    const int tx2 = tid & 31, ty2 = tid >> 5;

    const int ky0 = 1 - (ty & 1), kx0 = 1 - (tx & 1);
    const int hy = (ty >> 1) + 1 + (ty & 1);
    const int hx = (tx >> 1) + 1 + (tx & 1);

    auto load_stage = [&](int cib, int buf) {
        #pragma unroll
        for (int cl = 0; cl < CIB; cl++) {
            const float* ip = inb + (size_t)(cib + cl)*HWin;
            float* sp = &sIn[buf][cl*IW*IWP];
            for (int r = ty2; r < IW; r += 8) {
                int gy = iyb + r;
                bool rowok = (unsigned)gy < (unsigned)Hin;
                const float* rp = ip + (size_t)gy*Win;
                for (int c = tx2; c < IW; c += 32) {
                    int gx = ixb + c;
                    cp4(sp + r*IWP + c, rp + gx,
                        rowok && ((unsigned)gx < (unsigned)Win));
                }
            }
        }
        for (int i = tid; i < CIB*16*OCBt; i += 256) {
            int oc = i & (OCBt-1);
            int rest = i >> LOG_OCB;
            int kk = rest & 15, cl = rest >> 4;
            cp4(&sWt[buf][i], wt + ((size_t)(cib+cl)*Cout + (ocb+oc))*16 + kk, true);
        }
    };

    float acc[OCBt][2][2];
    #pragma unroll
    for (int o = 0; o < OCBt; o++) {
        acc[o][0][0] = 0.f; acc[o][0][1] = 0.f;
        acc[o][1][0] = 0.f; acc[o][1][1] = 0.f;
    }

    const int NB = Cin / CIB;
    load_stage(0, 0);
    cp_commit();

    for (int b = 0; b < NB; b++) {
        const int buf = b & 1;
        if (b + 1 < NB) {
            load_stage((b+1)*CIB, buf ^ 1);
            cp_commit();
            cp_wait<1>();
        } else {
            cp_wait<0>();
        }
        __syncthreads();

        #pragma unroll
        for (int cl = 0; cl < CIB; cl++) {
            const float* sI = &sIn[buf][cl*IW*IWP];
            const float* sW = &sWt[buf][cl*16*OCBt];

            float vin[2][2][2][2];   // [ey][tap_y][ex][tap_x]
            #pragma unroll
            for (int ey = 0; ey < 2; ey++)
            #pragma unroll
            for (int tyt = 0; tyt < 2; tyt++)
            #pragma unroll
            for (int ex = 0; ex < 2; ex++)
            #pragma unroll
            for (int txt = 0; txt < 2; txt++)
                vin[ey][tyt][ex][txt] = sI[(hy + 8*ey - tyt)*IWP + (hx + 8*ex - txt)];

            #pragma unroll
            for (int tyt = 0; tyt < 2; tyt++)
            #pragma unroll
            for (int txt = 0; txt < 2; txt++) {
                const int kk = (ky0 + 2*tyt)*4 + (kx0 + 2*txt);
                const float4* wp = (const float4*)(sW + kk*OCBt);
                float w[OCBt];
                #pragma unroll
                for (int j4 = 0; j4 < OCBt/4; j4++)
                    *(float4*)&w[j4*4] = wp[j4];
                #pragma unroll
                for (int ey = 0; ey < 2; ey++)
                #pragma unroll
                for (int ex = 0; ex < 2; ex++) {
                    float s = vin[ey][tyt][ex][txt];
                    #pragma unroll
                    for (int o = 0; o < OCBt; o++)
                        acc[o][ey][ex] = fmaf(w[o], s, acc[o][ey][ex]);
                }
            }
        }
        __syncthreads();
    }

    #pragma unroll
    for (int o = 0; o < OCBt; o++) {
        int c = ocb + o;
        float bv = bias ? __ldg(bias + c) : 0.f;
        #pragma unroll
        for (int ey = 0; ey < 2; ey++)
        #pragma unroll
        for (int ex = 0; ex < 2; ex++) {
            float v = acc[o][ey][ex];
            if (bias) v = __fadd_rn(v, bv);
            int oy = oy0 + ty + 16*ey, ox = ox0 + tx + 16*ex;
            if (act == 1)      v = (v > 0.f) ? v : __fmul_rn(0.01f, v);
            else if (act == 2) v = (v > 0.f) ? v : 0.f;
            out[(((size_t)n*Cout + c)*Hout + oy)*Wout + ox] = v;
        }
    }
}

// ---------------- RVQ (numerics locked: do not touch) ----------------
__global__ __launch_bounds__(256)
void cnorm_kernel(const float* __restrict__ cb, float* __restrict__ cn, int total)
{
    int warp = (blockIdx.x*256 + threadIdx.x) >> 5;
    int lane = threadIdx.x & 31;
    if (warp >= total) return;
    const float* p = cb + (size_t)warp*64;
    float a0 = p[lane], a1 = p[lane+32];
    float a = __fadd_rn(__fmul_rn(a0, a0), __fmul_rn(a1, a1));
    #pragma unroll
    for (int off = 16; off > 0; off >>= 1)
        a = __fadd_rn(a, __shfl_down_sync(0xffffffffu, a, off));
    if (lane == 0) cn[warp] = a;
}

__global__ __launch_bounds__(256)
void rvq_stage(float* __restrict__ r, float* __restrict__ qacc,
               const float* __restrict__ cb, const float* __restrict__ cnorm,
               float* __restrict__ idx_out, float* __restrict__ partials,
               int HW, int stage)
{
    __shared__ __align__(16) float sCt[64*32];   // [d][kk] 8KB
    __shared__ float sCn[32];
    __shared__ float sRed[256];

    const int t = blockIdx.x*256 + threadIdx.x;
    const int n = t / HW, p = t - n*HW;
    const size_t base = (size_t)n*64*HW + p;

    float rl[64];
    #pragma unroll
    for (int d = 0; d < 64; d++)
        rl[d] = r[base + (size_t)d*HW];
    float rn = 0.f;
    #pragma unroll
    for (int d = 0; d < 64; d++) rn = fmaf(rl[d], rl[d], rn);

    float best = 3.4e38f; int bidx = 0;
    for (int kb = 0; kb < 512; kb += 32) {
        __syncthreads();
        for (int i = threadIdx.x; i < 64*32; i += 256) {
            int kk = i & 31, d = i >> 5;
            sCt[i] = __ldg(cb + (size_t)(kb + kk)*64 + d);
        }
        if (threadIdx.x < 32) sCn[threadIdx.x] = cnorm[kb + threadIdx.x];
        __syncthreads();

        float dot[32];
        #pragma unroll
        for (int j = 0; j < 32; j++) dot[j] = 0.f;
        #pragma unroll
        for (int d = 0; d < 64; d++) {
            float rt = rl[d];
            const float4* cp = (const float4*)(sCt + d*32);
            #pragma unroll
            for (int j4 = 0; j4 < 8; j4++) {
                float4 c4 = cp[j4];
                dot[j4*4+0] = fmaf(rt, c4.x, dot[j4*4+0]);
                dot[j4*4+1] = fmaf(rt, c4.y, dot[j4*4+1]);
                dot[j4*4+2] = fmaf(rt, c4.z, dot[j4*4+2]);
                dot[j4*4+3] = fmaf(rt, c4.w, dot[j4*4+3]);
            }
        }
        #pragma unroll
        for (int j = 0; j < 32; j++) {
            float dist = __fadd_rn(__fadd_rn(rn, -__fmul_rn(2.f, dot[j])), sCn[j]);
            if (dist < best) { best = dist; bidx = kb + j; }
        }
    }

    float lsum = 0.f;
    const float* cq = cb + (size_t)bidx*64;
    #pragma unroll
    for (int d = 0; d < 64; d++) {
        float q = __ldg(cq + d);
        float diff = __fadd_rn(q, -rl[d]);
        lsum = fmaf(diff, diff, lsum);
        float q_st = __fadd_rn(rl[d], diff);
        size_t ii = base + (size_t)d*HW;
        if (stage == 0) qacc[ii] = q_st;
        else            qacc[ii] = __fadd_rn(qacc[ii], q_st);
        r[ii] = __fadd_rn(rl[d], -q);
    }
    idx_out[(size_t)t*4 + stage] = (float)bidx;

    sRed[threadIdx.x] = lsum;
    __syncthreads();
    for (int sft = 128; sft > 0; sft >>= 1) {
        if (threadIdx.x < sft) sRed[threadIdx.x] += sRed[threadIdx.x + sft];
        __syncthreads();
    }
    if (threadIdx.x == 0) partials[stage*256 + blockIdx.x] = sRed[0];
}

__global__ __launch_bounds__(256)
void loss_finalize(const float* __restrict__ partials, float* __restrict__ loss_out, float scale)
{
    __shared__ float sRed[256];
    int stage = blockIdx.x;
    sRed[threadIdx.x] = partials[stage*256 + threadIdx.x];
    __syncthreads();
    for (int sft = 128; sft > 0; sft >>= 1) {
        if (threadIdx.x < sft) sRed[threadIdx.x] += sRed[threadIdx.x + sft];
        __syncthreads();
    }
    if (threadIdx.x == 0) loss_out[stage] = 0.25f * (sRed[0] * scale);
}

// ---------------- launch ----------------
extern "C" void kernel_launch(void* const* d_in, const int* in_sizes, int n_in,
                              void* d_out, int out_size)
{
    const float* x     = (const float*)d_in[0];
    const float* e1w   = (const float*)d_in[1];
    const float* e1b   = (const float*)d_in[2];
    const float* e2w   = (const float*)d_in[3];
    const float* e2b   = (const float*)d_in[4];
    const float* e3w   = (const float*)d_in[5];
    const float* e3b   = (const float*)d_in[6];
    const float* r1aw  = (const float*)d_in[7];
    const float* r1bw  = (const float*)d_in[8];
    const float* r2aw  = (const float*)d_in[9];
    const float* r2bw  = (const float*)d_in[10];
    const float* e4w   = (const float*)d_in[11];
    const float* e4b   = (const float*)d_in[12];
    const float* cbs   = (const float*)d_in[13];
    const float* d1w   = (const float*)d_in[14];
    const float* d1b   = (const float*)d_in[15];
    const float* dr1aw = (const float*)d_in[16];
    const float* dr1bw = (const float*)d_in[17];
    const float* dr2aw = (const float*)d_in[18];
    const float* dr2bw = (const float*)d_in[19];
    const float* dt1w  = (const float*)d_in[20];
    const float* dt1b  = (const float*)d_in[21];
    const float* dt2w  = (const float*)d_in[22];
    const float* dt2b  = (const float*)d_in[23];

    float* out = (float*)d_out;
    float* recons  = out;                        // 16*4*256*256
    float* idxout  = out + (size_t)16*4*256*256; // 16*64*64*4
    float* lossout = idxout + (size_t)16*64*64*4;// 4

    float *A,*B,*C,*D,*R,*Q,*CN,*P;
    cudaGetSymbolAddress((void**)&A,  g_bufA);
    cudaGetSymbolAddress((void**)&B,  g_bufB);
    cudaGetSymbolAddress((void**)&C,  g_bufC);
    cudaGetSymbolAddress((void**)&D,  g_bufD);
    cudaGetSymbolAddress((void**)&R,  g_r);
    cudaGetSymbolAddress((void**)&Q,  g_q);
    cudaGetSymbolAddress((void**)&CN, g_cnorm);
    cudaGetSymbolAddress((void**)&P,  g_partials);

    cnorm_kernel<<<256, 256>>>(cbs, CN, 4*512);

    // ---- encoder ----
    conv_pipe<4,2,1><<<dim3(4,4,64), 256>>>(x, e1w, e1b, nullptr, A,
                                            16,4,256,256, 64,128,128, 1, 1);
    conv_pipe<4,2,1><<<dim3(2,2,128), 256>>>(A, e2w, e2b, nullptr, B,
                                             16,64,128,128, 128,64,64, 1, 1);
    conv_pipe<3,1,4><<<dim3(2,2,128), 256>>>(B, e3w, e3b, nullptr, C,
                                             16,128,64,64, 128,64,64, 1, 1);
    conv_pipe<3,1,4><<<dim3(2,2,128), 256>>>(C, r1aw, nullptr, nullptr, D,
                                             16,128,64,64, 128,64,64, 1, 2);
    conv_pipe<1,1,4><<<dim3(2,2,128), 256>>>(D, r1bw, nullptr, C, B,
                                             16,128,64,64, 128,64,64, 0, 0);
    conv_pipe<3,1,4><<<dim3(2,2,128), 256>>>(B, r2aw, nullptr, nullptr, D,
                                             16,128,64,64, 128,64,64, 1, 2);
    conv_pipe<1,1,4><<<dim3(2,2,128), 256>>>(D, r2bw, nullptr, B, C,
                                             16,128,64,64, 128,64,64, 0, 1);
    conv_pipe<1,1,4><<<dim3(2,2,64), 256>>>(C, e4w, e4b, nullptr, R,
                                            16,128,64,64, 64,64,64, 0, 1);

    // ---- residual VQ: 4 stages ----
    for (int s = 0; s < 4; s++)
        rvq_stage<<<256, 256>>>(R, Q, cbs + (size_t)s*512*64, CN + s*512,
                                idxout, P, 64*64, s);
    loss_finalize<<<4, 256>>>(P, lossout, 1.f/(65536.f*64.f));

    // ---- decoder ----
    conv_pipe<3,1,4><<<dim3(2,2,128), 256>>>(Q, d1w, d1b, nullptr, B,
                                             16,64,64,64, 128,64,64, 1, 1);
    conv_pipe<3,1,4><<<dim3(2,2,128), 256>>>(B, dr1aw, nullptr, nullptr, D,
                                             16,128,64,64, 128,64,64, 1, 2);
    conv_pipe<1,1,4><<<dim3(2,2,128), 256>>>(D, dr1bw, nullptr, B, C,
                                             16,128,64,64, 128,64,64, 0, 0);
    conv_pipe<3,1,4><<<dim3(2,2,128), 256>>>(C, dr2aw, nullptr, nullptr, D,
                                             16,128,64,64, 128,64,64, 1, 2);
    conv_pipe<1,1,4><<<dim3(2,2,128), 256>>>(D, dr2bw, nullptr, C, B,
                                             16,128,64,64, 128,64,64, 0, 1);
    convT_pipe<16,4,8><<<dim3(4,4,64), 256>>>(B, dt1w, dt1b, A,
                                              16,128,64,64, 64, 1);
    convT_pipe<4,2,8><<<dim3(8,8,16), 256>>>(A, dt2w, dt2b, recons,
                                             16,64,128,128, 4, 2);
}

// round 9
// speedup vs baseline: 1.5068x; 1.1292x over previous
#include <cuda_runtime.h>
#include <cuda_bf16.h>
#include <cstddef>
#include <cstdint>

// ---------------- scratch (device globals; no allocation allowed) ----------------
__device__ float g_bufA[16u*64u*128u*128u];   // 16.78M floats (e1 out / dt1 out)
__device__ float g_bufB[16u*128u*64u*64u];    // 8.39M
__device__ float g_bufC[16u*128u*64u*64u];
__device__ float g_bufD[16u*128u*64u*64u];
__device__ float g_r  [16u*64u*64u*64u];      // residual tokens (NCHW view)
__device__ float g_q  [16u*64u*64u*64u];      // quantized accumulation (NCHW view)
__device__ float g_cnorm[4*512];
__device__ float g_partials[4*256];

// ---------------- cp.async helpers ----------------
__device__ __forceinline__ void cp4(void* smem_dst, const void* gsrc, bool pred) {
    uint32_t s = (uint32_t)__cvta_generic_to_shared(smem_dst);
    int sz = pred ? 4 : 0;               // src-size 0 -> zero-fill (free OOB padding)
    asm volatile("cp.async.ca.shared.global [%0], [%1], 4, %2;" :: "r"(s), "l"(gsrc), "r"(sz));
}
__device__ __forceinline__ void cp_commit() {
    asm volatile("cp.async.commit_group;");
}
template<int Nw>
__device__ __forceinline__ void cp_wait() {
    asm volatile("cp.async.wait_group %0;" :: "n"(Nw));
}

// ---------------- pipelined register-tiled direct convolution (fp32; numerics locked) ----------
// Per-output accumulation: ci asc, (ky,kx) asc, single FFMA chain — bit-identical
// to the round-3/4/5 passing kernels.
template<int K, int S, int CIB>
__global__ __launch_bounds__(256, 2)
void conv_pipe(const float* __restrict__ in, const float* __restrict__ wt,
               const float* __restrict__ bias, const float* __restrict__ resid,
               float* __restrict__ out,
               int N, int Cin, int Hin, int Win, int Cout, int Hout, int Wout,
               int pad, int act)
{
    constexpr int IW  = 32*S + K - S;
    constexpr int IWP = IW | 1;
    constexpr int KK  = K*K;
    __shared__ float sIn[2][CIB*IW*IWP];
    __shared__ __align__(16) float sWt[2][CIB*KK*16];

    const int tid = threadIdx.x;
    const int chunks = Cout >> 4;
    const int n   = blockIdx.z / chunks;
    const int ocb = (blockIdx.z - n*chunks) << 4;
    const int ox0 = blockIdx.x << 5, oy0 = blockIdx.y << 5;
    const int tx = tid & 15, ty = tid >> 4;
    const int ix0 = ox0*S - pad, iy0 = oy0*S - pad;
    const int HWin = Hin*Win;
    const float* inb = in + (size_t)n*Cin*HWin;
    const int tx2 = tid & 31, ty2 = tid >> 5;

    auto load_stage = [&](int cib, int buf) {
        #pragma unroll
        for (int cl = 0; cl < CIB; cl++) {
            const float* ip = inb + (size_t)(cib + cl)*HWin;
            float* sp = &sIn[buf][cl*IW*IWP];
            for (int r = ty2; r < IW; r += 8) {
                int gy = iy0 + r;
                bool rowok = (unsigned)gy < (unsigned)Hin;
                const float* rp = ip + (size_t)gy*Win;
                for (int c = tx2; c < IW; c += 32) {
                    int gx = ix0 + c;
                    cp4(sp + r*IWP + c, rp + gx,
                        rowok && ((unsigned)gx < (unsigned)Win));
                }
            }
        }
        for (int i = tid; i < CIB*KK*16; i += 256) {
            int oc = i & 15;
            int rest = i >> 4;
            int kk = rest % KK, cl = rest / KK;
            cp4(&sWt[buf][i], wt + ((size_t)(ocb+oc)*Cin + (cib+cl))*KK + kk, true);
        }
    };

    float acc[16][2][2];
    #pragma unroll
    for (int o = 0; o < 16; o++) {
        acc[o][0][0] = 0.f; acc[o][0][1] = 0.f;
        acc[o][1][0] = 0.f; acc[o][1][1] = 0.f;
    }

    const int NB = Cin / CIB;
    load_stage(0, 0);
    cp_commit();

    for (int b = 0; b < NB; b++) {
        const int buf = b & 1;
        if (b + 1 < NB) {
            load_stage((b+1)*CIB, buf ^ 1);
            cp_commit();
            cp_wait<1>();
        } else {
            cp_wait<0>();
        }
        __syncthreads();

        #pragma unroll
        for (int cl = 0; cl < CIB; cl++) {
            const float* sI = &sIn[buf][cl*IW*IWP];
            const float* sW = &sWt[buf][cl*KK*16];
            if constexpr (S == 1) {
                float inr[K+1][K+1];
                #pragma unroll
                for (int r = 0; r < K+1; r++)
                    #pragma unroll
                    for (int c = 0; c < K+1; c++)
                        inr[r][c] = sI[(ty*2 + r)*IWP + tx*2 + c];
                #pragma unroll
                for (int ky = 0; ky < K; ky++)
                #pragma unroll
                for (int kx = 0; kx < K; kx++) {
                    const float4* wp = (const float4*)(sW + (ky*K + kx)*16);
                    float w[16];
                    *(float4*)&w[0]  = wp[0];
                    *(float4*)&w[4]  = wp[1];
                    *(float4*)&w[8]  = wp[2];
                    *(float4*)&w[12] = wp[3];
                    #pragma unroll
                    for (int dy = 0; dy < 2; dy++)
                    #pragma unroll
                    for (int dx = 0; dx < 2; dx++) {
                        float s = inr[ky+dy][kx+dx];
                        #pragma unroll
                        for (int o = 0; o < 16; o++)
                            acc[o][dy][dx] = fmaf(w[o], s, acc[o][dy][dx]);
                    }
                }
            } else {
                #pragma unroll
                for (int ky = 0; ky < K; ky++)
                #pragma unroll
                for (int kx = 0; kx < K; kx++) {
                    const float4* wp = (const float4*)(sW + (ky*K + kx)*16);
                    float w[16];
                    *(float4*)&w[0]  = wp[0];
                    *(float4*)&w[4]  = wp[1];
                    *(float4*)&w[8]  = wp[2];
                    *(float4*)&w[12] = wp[3];
                    #pragma unroll
                    for (int dy = 0; dy < 2; dy++)
                    #pragma unroll
                    for (int dx = 0; dx < 2; dx++) {
                        float s = sI[((ty*2+dy)*S + ky)*IWP + (tx*2+dx)*S + kx];
                        #pragma unroll
                        for (int o = 0; o < 16; o++)
                            acc[o][dy][dx] = fmaf(w[o], s, acc[o][dy][dx]);
                    }
                }
            }
        }
        __syncthreads();
    }

    const int oy = oy0 + ty*2, ox = ox0 + tx*2;
    #pragma unroll
    for (int o = 0; o < 16; o++) {
        int c = ocb + o;
        float bv = bias ? __ldg(bias + c) : 0.f;
        #pragma unroll
        for (int dy = 0; dy < 2; dy++)
        #pragma unroll
        for (int dx = 0; dx < 2; dx++) {
            float v = acc[o][dy][dx];
            if (bias)  v = __fadd_rn(v, bv);
            size_t oi = (((size_t)n*Cout + c)*Hout + (oy+dy))*Wout + (ox+dx);
            if (resid) v = __fadd_rn(v, resid[oi]);
            if (act == 1)      v = (v > 0.f) ? v : __fmul_rn(0.01f, v);
            else if (act == 2) v = (v > 0.f) ? v : 0.f;
            out[oi] = v;
        }
    }
}

// ---------------- direct 1x1 convolution (GEMM-style, no tile staging) ----------------
// Thread owns 4 consecutive pixels; ci asc single FFMA chain per output — bit-identical.
__global__ __launch_bounds__(256)
void conv1x1(const float* __restrict__ in, const float* __restrict__ wt,
             const float* __restrict__ bias, const float* __restrict__ resid,
             float* __restrict__ out,
             int Cin, int HW, int Cout, int act)
{
    __shared__ __align__(16) float sW[128*16];   // [ci][oc], Cin<=128

    const int tid = threadIdx.x;
    const int ocb = blockIdx.y << 4;
    for (int i = tid; i < Cin*16; i += 256) {
        int oc = i & 15, ci = i >> 4;
        sW[i] = __ldg(wt + (size_t)(ocb+oc)*Cin + ci);
    }
    __syncthreads();

    const int gp = (blockIdx.x*256 + tid) * 4;
    const int n = gp / HW, p = gp - n*HW;
    const float* ip = in + ((size_t)n*Cin)*HW + p;

    float acc[16][4];
    #pragma unroll
    for (int o = 0; o < 16; o++)
        #pragma unroll
        for (int j = 0; j < 4; j++) acc[o][j] = 0.f;

    #pragma unroll 2
    for (int ci = 0; ci < Cin; ci++) {
        float4 xv = *(const float4*)(ip + (size_t)ci*HW);
        const float4* wp = (const float4*)(sW + ci*16);
        float w[16];
        *(float4*)&w[0]  = wp[0];
        *(float4*)&w[4]  = wp[1];
        *(float4*)&w[8]  = wp[2];
        *(float4*)&w[12] = wp[3];
        #pragma unroll
        for (int o = 0; o < 16; o++) {
            acc[o][0] = fmaf(w[o], xv.x, acc[o][0]);
            acc[o][1] = fmaf(w[o], xv.y, acc[o][1]);
            acc[o][2] = fmaf(w[o], xv.z, acc[o][2]);
            acc[o][3] = fmaf(w[o], xv.w, acc[o][3]);
        }
    }

    #pragma unroll
    for (int o = 0; o < 16; o++) {
        int c = ocb + o;
        float bv = bias ? __ldg(bias + c) : 0.f;
        size_t ob = ((size_t)n*Cout + c)*HW + p;
        #pragma unroll
        for (int j = 0; j < 4; j++) {
            float v = acc[o][j];
            if (bias)  v = __fadd_rn(v, bv);
            if (resid) v = __fadd_rn(v, resid[ob + j]);
            if (act == 1)      v = (v > 0.f) ? v : __fmul_rn(0.01f, v);
            else if (act == 2) v = (v > 0.f) ? v : 0.f;
            out[ob + j] = v;
        }
    }
}

// ---------------- pipelined transposed conv (k=4,s=2,p=1), fp32, torch layout (in,out,4,4) ----
template<int OCBt, int LOG_OCB, int CIB>
__global__ __launch_bounds__(256, 2)
void convT_pipe(const float* __restrict__ in, const float* __restrict__ wt,
                const float* __restrict__ bias, float* __restrict__ out,
                int N, int Cin, int Hin, int Win, int Cout, int act)
{
    constexpr int IW = 18, IWP = 19;
    __shared__ float sIn[2][CIB*IW*IWP];
    __shared__ __align__(16) float sWt[2][CIB*16*OCBt];

    const int tid = threadIdx.x;
    const int Hout = Hin*2, Wout = Win*2;
    const int chunks = Cout >> LOG_OCB;
    const int n   = blockIdx.z / chunks;
    const int ocb = (blockIdx.z - n*chunks) << LOG_OCB;
    const int ox0 = blockIdx.x << 5, oy0 = blockIdx.y << 5;
    const int tx = tid & 15, ty = tid >> 4;
    const int iyb = (oy0 >> 1) - 1, ixb = (ox0 >> 1) - 1;
    const int HWin = Hin*Win;
    const float* inb = in + (size_t)n*Cin*HWin;
    const int tx2 = tid & 31, ty2 = tid >> 5;

    const int ky0 = 1 - (ty & 1), kx0 = 1 - (tx & 1);
    const int hy = (ty >> 1) + 1 + (ty & 1);
    const int hx = (tx >> 1) + 1 + (tx & 1);

    auto load_stage = [&](int cib, int buf) {
        #pragma unroll
        for (int cl = 0; cl < CIB; cl++) {
            const float* ip = inb + (size_t)(cib + cl)*HWin;
            float* sp = &sIn[buf][cl*IW*IWP];
            for (int r = ty2; r < IW; r += 8) {
                int gy = iyb + r;
                bool rowok = (unsigned)gy < (unsigned)Hin;
                const float* rp = ip + (size_t)gy*Win;
                for (int c = tx2; c < IW; c += 32) {
                    int gx = ixb + c;
                    cp4(sp + r*IWP + c, rp + gx,
                        rowok && ((unsigned)gx < (unsigned)Win));
                }
            }
        }
        for (int i = tid; i < CIB*16*OCBt; i += 256) {
            int oc = i & (OCBt-1);
            int rest = i >> LOG_OCB;
            int kk = rest & 15, cl = rest >> 4;
            cp4(&sWt[buf][i], wt + ((size_t)(cib+cl)*Cout + (ocb+oc))*16 + kk, true);
        }
    };

    float acc[OCBt][2][2];
    #pragma unroll
    for (int o = 0; o < OCBt; o++) {
        acc[o][0][0] = 0.f; acc[o][0][1] = 0.f;
        acc[o][1][0] = 0.f; acc[o][1][1] = 0.f;
    }

    const int NB = Cin / CIB;
    load_stage(0, 0);
    cp_commit();

    for (int b = 0; b < NB; b++) {
        const int buf = b & 1;
        if (b + 1 < NB) {
            load_stage((b+1)*CIB, buf ^ 1);
            cp_commit();
            cp_wait<1>();
        } else {
            cp_wait<0>();
        }
        __syncthreads();

        #pragma unroll
        for (int cl = 0; cl < CIB; cl++) {
            const float* sI = &sIn[buf][cl*IW*IWP];
            const float* sW = &sWt[buf][cl*16*OCBt];

            float vin[2][2][2][2];   // [ey][tap_y][ex][tap_x]
            #pragma unroll
            for (int ey = 0; ey < 2; ey++)
            #pragma unroll
            for (int tyt = 0; tyt < 2; tyt++)
            #pragma unroll
            for (int ex = 0; ex < 2; ex++)
            #pragma unroll
            for (int txt = 0; txt < 2; txt++)
                vin[ey][tyt][ex][txt] = sI[(hy + 8*ey - tyt)*IWP + (hx + 8*ex - txt)];

            #pragma unroll
            for (int tyt = 0; tyt < 2; tyt++)
            #pragma unroll
            for (int txt = 0; txt < 2; txt++) {
                const int kk = (ky0 + 2*tyt)*4 + (kx0 + 2*txt);
                const float4* wp = (const float4*)(sW + kk*OCBt);
                float w[OCBt];
                #pragma unroll
                for (int j4 = 0; j4 < OCBt/4; j4++)
                    *(float4*)&w[j4*4] = wp[j4];
                #pragma unroll
                for (int ey = 0; ey < 2; ey++)
                #pragma unroll
                for (int ex = 0; ex < 2; ex++) {
                    float s = vin[ey][tyt][ex][txt];
                    #pragma unroll
                    for (int o = 0; o < OCBt; o++)
                        acc[o][ey][ex] = fmaf(w[o], s, acc[o][ey][ex]);
                }
            }
        }
        __syncthreads();
    }

    #pragma unroll
    for (int o = 0; o < OCBt; o++) {
        int c = ocb + o;
        float bv = bias ? __ldg(bias + c) : 0.f;
        #pragma unroll
        for (int ey = 0; ey < 2; ey++)
        #pragma unroll
        for (int ex = 0; ex < 2; ex++) {
            float v = acc[o][ey][ex];
            if (bias) v = __fadd_rn(v, bv);
            int oy = oy0 + ty + 16*ey, ox = ox0 + tx + 16*ex;
            if (act == 1)      v = (v > 0.f) ? v : __fmul_rn(0.01f, v);
            else if (act == 2) v = (v > 0.f) ? v : 0.f;
            out[(((size_t)n*Cout + c)*Hout + oy)*Wout + ox] = v;
        }
    }
}

// ---------------- RVQ (numerics locked: identical value chains) ----------------
__global__ __launch_bounds__(256)
void cnorm_kernel(const float* __restrict__ cb, float* __restrict__ cn, int total)
{
    int warp = (blockIdx.x*256 + threadIdx.x) >> 5;
    int lane = threadIdx.x & 31;
    if (warp >= total) return;
    const float* p = cb + (size_t)warp*64;
    float a0 = p[lane], a1 = p[lane+32];
    float a = __fadd_rn(__fmul_rn(a0, a0), __fmul_rn(a1, a1));
    #pragma unroll
    for (int off = 16; off > 0; off >>= 1)
        a = __fadd_rn(a, __shfl_down_sync(0xffffffffu, a, off));
    if (lane == 0) cn[warp] = a;
}

// All 4 RVQ stages fused: rl / qa live in registers across stages; no intermediate
// global r/qacc traffic. Every rounded value and its order matches the 4-kernel version.
__global__ __launch_bounds__(256)
void rvq_fused(const float* __restrict__ r_in, float* __restrict__ qacc,
               const float* __restrict__ cbs, const float* __restrict__ cnorm,
               float* __restrict__ idx_out, float* __restrict__ partials, int HW)
{
    __shared__ __align__(16) float sCt[64*32];
    __shared__ float sCn[32];
    __shared__ float sRed[256];

    const int t = blockIdx.x*256 + threadIdx.x;
    const int n = t / HW, p = t - n*HW;
    const size_t base = (size_t)n*64*HW + p;

    float rl[64], qa[64];
    #pragma unroll
    for (int d = 0; d < 64; d++)
        rl[d] = r_in[base + (size_t)d*HW];

    for (int stage = 0; stage < 4; stage++) {
        const float* cb = cbs + (size_t)stage*512*64;
        const float* cn = cnorm + stage*512;

        float rn = 0.f;
        #pragma unroll
        for (int d = 0; d < 64; d++) rn = fmaf(rl[d], rl[d], rn);

        float best = 3.4e38f; int bidx = 0;
        for (int kb = 0; kb < 512; kb += 32) {
            __syncthreads();
            for (int i = threadIdx.x; i < 64*32; i += 256) {
                int kk = i & 31, d = i >> 5;
                sCt[i] = __ldg(cb + (size_t)(kb + kk)*64 + d);
            }
            if (threadIdx.x < 32) sCn[threadIdx.x] = cn[kb + threadIdx.x];
            __syncthreads();

            float dot[32];
            #pragma unroll
            for (int j = 0; j < 32; j++) dot[j] = 0.f;
            #pragma unroll
            for (int d = 0; d < 64; d++) {
                float rt = rl[d];
                const float4* cp = (const float4*)(sCt + d*32);
                #pragma unroll
                for (int j4 = 0; j4 < 8; j4++) {
                    float4 c4 = cp[j4];
                    dot[j4*4+0] = fmaf(rt, c4.x, dot[j4*4+0]);
                    dot[j4*4+1] = fmaf(rt, c4.y, dot[j4*4+1]);
                    dot[j4*4+2] = fmaf(rt, c4.z, dot[j4*4+2]);
                    dot[j4*4+3] = fmaf(rt, c4.w, dot[j4*4+3]);
                }
            }
            #pragma unroll
            for (int j = 0; j < 32; j++) {
                float dist = __fadd_rn(__fadd_rn(rn, -__fmul_rn(2.f, dot[j])), sCn[j]);
                if (dist < best) { best = dist; bidx = kb + j; }
            }
        }

        float lsum = 0.f;
        const float* cq = cb + (size_t)bidx*64;
        #pragma unroll
        for (int d = 0; d < 64; d++) {
            float q = __ldg(cq + d);
            float diff = __fadd_rn(q, -rl[d]);
            lsum = fmaf(diff, diff, lsum);
            float q_st = __fadd_rn(rl[d], diff);
            if (stage == 0) qa[d] = q_st;
            else            qa[d] = __fadd_rn(qa[d], q_st);
            rl[d] = __fadd_rn(rl[d], -q);
        }
        idx_out[(size_t)t*4 + stage] = (float)bidx;

        __syncthreads();
        sRed[threadIdx.x] = lsum;
        __syncthreads();
        for (int sft = 128; sft > 0; sft >>= 1) {
            if (threadIdx.x < sft) sRed[threadIdx.x] += sRed[threadIdx.x + sft];
            __syncthreads();
        }
        if (threadIdx.x == 0) partials[stage*256 + blockIdx.x] = sRed[0];
    }

    #pragma unroll
    for (int d = 0; d < 64; d++)
        qacc[base + (size_t)d*HW] = qa[d];
}

__global__ __launch_bounds__(256)
void loss_finalize(const float* __restrict__ partials, float* __restrict__ loss_out, float scale)
{
    __shared__ float sRed[256];
    int stage = blockIdx.x;
    sRed[threadIdx.x] = partials[stage*256 + threadIdx.x];
    __syncthreads();
    for (int sft = 128; sft > 0; sft >>= 1) {
        if (threadIdx.x < sft) sRed[threadIdx.x] += sRed[threadIdx.x + sft];
        __syncthreads();
    }
    if (threadIdx.x == 0) loss_out[stage] = 0.25f * (sRed[0] * scale);
}

// ---------------- launch ----------------
extern "C" void kernel_launch(void* const* d_in, const int* in_sizes, int n_in,
                              void* d_out, int out_size)
{
    const float* x     = (const float*)d_in[0];
    const float* e1w   = (const float*)d_in[1];
    const float* e1b   = (const float*)d_in[2];
    const float* e2w   = (const float*)d_in[3];
    const float* e2b   = (const float*)d_in[4];
    const float* e3w   = (const float*)d_in[5];
    const float* e3b   = (const float*)d_in[6];
    const float* r1aw  = (const float*)d_in[7];
    const float* r1bw  = (const float*)d_in[8];
    const float* r2aw  = (const float*)d_in[9];
    const float* r2bw  = (const float*)d_in[10];
    const float* e4w   = (const float*)d_in[11];
    const float* e4b   = (const float*)d_in[12];
    const float* cbs   = (const float*)d_in[13];
    const float* d1w   = (const float*)d_in[14];
    const float* d1b   = (const float*)d_in[15];
    const float* dr1aw = (const float*)d_in[16];
    const float* dr1bw = (const float*)d_in[17];
    const float* dr2aw = (const float*)d_in[18];
    const float* dr2bw = (const float*)d_in[19];
    const float* dt1w  = (const float*)d_in[20];
    const float* dt1b  = (const float*)d_in[21];
    const float* dt2w  = (const float*)d_in[22];
    const float* dt2b  = (const float*)d_in[23];

    float* out = (float*)d_out;
    float* recons  = out;                        // 16*4*256*256
    float* idxout  = out + (size_t)16*4*256*256; // 16*64*64*4
    float* lossout = idxout + (size_t)16*64*64*4;// 4

    float *A,*B,*C,*D,*R,*Q,*CN,*P;
    cudaGetSymbolAddress((void**)&A,  g_bufA);
    cudaGetSymbolAddress((void**)&B,  g_bufB);
    cudaGetSymbolAddress((void**)&C,  g_bufC);
    cudaGetSymbolAddress((void**)&D,  g_bufD);
    cudaGetSymbolAddress((void**)&R,  g_r);
    cudaGetSymbolAddress((void**)&Q,  g_q);
    cudaGetSymbolAddress((void**)&CN, g_cnorm);
    cudaGetSymbolAddress((void**)&P,  g_partials);

    cnorm_kernel<<<256, 256>>>(cbs, CN, 4*512);

    // ---- encoder (fp32, numerics locked) ----
    conv_pipe<4,2,1><<<dim3(4,4,64), 256>>>(x, e1w, e1b, nullptr, A,
                                            16,4,256,256, 64,128,128, 1, 1);
    conv_pipe<4,2,1><<<dim3(2,2,128), 256>>>(A, e2w, e2b, nullptr, B,
                                             16,64,128,128, 128,64,64, 1, 1);
    conv_pipe<3,1,4><<<dim3(2,2,128), 256>>>(B, e3w, e3b, nullptr, C,
                                             16,128,64,64, 128,64,64, 1, 1);
    conv_pipe<3,1,4><<<dim3(2,2,128), 256>>>(C, r1aw, nullptr, nullptr, D,
                                             16,128,64,64, 128,64,64, 1, 2);
    conv1x1<<<dim3(64,8), 256>>>(D, r1bw, nullptr, C, B, 128, 4096, 128, 0);
    conv_pipe<3,1,4><<<dim3(2,2,128), 256>>>(B, r2aw, nullptr, nullptr, D,
                                             16,128,64,64, 128,64,64, 1, 2);
    conv1x1<<<dim3(64,8), 256>>>(D, r2bw, nullptr, B, C, 128, 4096, 128, 1);
    conv1x1<<<dim3(64,4), 256>>>(C, e4w, e4b, nullptr, R, 128, 4096, 64, 1);

    // ---- residual VQ: 4 stages fused ----
    rvq_fused<<<256, 256>>>(R, Q, cbs, CN, idxout, P, 64*64);
    loss_finalize<<<4, 256>>>(P, lossout, 1.f/(65536.f*64.f));

    // ---- decoder (fp32, numerics locked) ----
    conv_pipe<3,1,4><<<dim3(2,2,128), 256>>>(Q, d1w, d1b, nullptr, B,
                                             16,64,64,64, 128,64,64, 1, 1);
    conv_pipe<3,1,4><<<dim3(2,2,128), 256>>>(B, dr1aw, nullptr, nullptr, D,
                                             16,128,64,64, 128,64,64, 1, 2);
    conv1x1<<<dim3(64,8), 256>>>(D, dr1bw, nullptr, B, C, 128, 4096, 128, 0);
    conv_pipe<3,1,4><<<dim3(2,2,128), 256>>>(C, dr2aw, nullptr, nullptr, D,
                                             16,128,64,64, 128,64,64, 1, 2);
    conv1x1<<<dim3(64,8), 256>>>(D, dr2bw, nullptr, C, B, 128, 4096, 128, 1);
    convT_pipe<16,4,8><<<dim3(4,4,64), 256>>>(B, dt1w, dt1b, A,
                                              16,128,64,64, 64, 1);
    convT_pipe<4,2,8><<<dim3(8,8,16), 256>>>(A, dt2w, dt2b, recons,
                                             16,64,128,128, 4, 2);
}

// round 10
// speedup vs baseline: 1.7219x; 1.1428x over previous
#include <cuda_runtime.h>
#include <cuda_bf16.h>
#include <cstddef>
#include <cstdint>

// ---------------- scratch (device globals; no allocation allowed) ----------------
__device__ float g_bufA[16u*64u*128u*128u];   // 16.78M floats (e1 out / dt1 out)
__device__ float g_bufB[16u*128u*64u*64u];    // 8.39M
__device__ float g_bufC[16u*128u*64u*64u];
__device__ float g_bufD[16u*128u*64u*64u];
__device__ float g_r  [16u*64u*64u*64u];      // residual tokens (NCHW view)
__device__ float g_q  [16u*64u*64u*64u];      // quantized accumulation (NCHW view)
__device__ float g_cnorm[4*512];
__device__ float g_partials[4*256];

// ---------------- packed fp32x2 helpers (two independent IEEE fp32 lanes) ----------------
__device__ __forceinline__ unsigned long long f2pack(float lo, float hi) {
    unsigned long long r;
    asm("mov.b64 %0, {%1, %2};" : "=l"(r) : "f"(lo), "f"(hi));
    return r;
}
__device__ __forceinline__ unsigned long long ffma2(unsigned long long a,
                                                    unsigned long long b,
                                                    unsigned long long c) {
    unsigned long long d;
    asm("fma.rn.f32x2 %0, %1, %2, %3;" : "=l"(d) : "l"(a), "l"(b), "l"(c));
    return d;
}
__device__ __forceinline__ float2 f2unpack(unsigned long long v) {
    float2 f;
    asm("mov.b64 {%0, %1}, %2;" : "=f"(f.x), "=f"(f.y) : "l"(v));
    return f;
}

// ---------------- cp.async helpers ----------------
__device__ __forceinline__ void cp4(void* smem_dst, const void* gsrc, bool pred) {
    uint32_t s = (uint32_t)__cvta_generic_to_shared(smem_dst);
    int sz = pred ? 4 : 0;               // src-size 0 -> zero-fill (free OOB padding)
    asm volatile("cp.async.ca.shared.global [%0], [%1], 4, %2;" :: "r"(s), "l"(gsrc), "r"(sz));
}
__device__ __forceinline__ void cp_commit() {
    asm volatile("cp.async.commit_group;");
}
template<int Nw>
__device__ __forceinline__ void cp_wait() {
    asm volatile("cp.async.wait_group %0;" :: "n"(Nw));
}

// ---------------- pipelined register-tiled direct convolution (fp32; numerics locked) ----------
// Per-output accumulation: ci asc, (ky,kx) asc, single fma chain per output.
// FFMA2 packs oc pairs: each half-lane chain is bit-identical to the scalar version.
template<int K, int S, int CIB>
__global__ __launch_bounds__(256, 2)
void conv_pipe(const float* __restrict__ in, const float* __restrict__ wt,
               const float* __restrict__ bias, const float* __restrict__ resid,
               float* __restrict__ out,
               int N, int Cin, int Hin, int Win, int Cout, int Hout, int Wout,
               int pad, int act)
{
    constexpr int IW  = 32*S + K - S;
    constexpr int IWP = IW | 1;
    constexpr int KK  = K*K;
    __shared__ float sIn[2][CIB*IW*IWP];
    __shared__ __align__(16) float sWt[2][CIB*KK*16];

    const int tid = threadIdx.x;
    const int chunks = Cout >> 4;
    const int n   = blockIdx.z / chunks;
    const int ocb = (blockIdx.z - n*chunks) << 4;
    const int ox0 = blockIdx.x << 5, oy0 = blockIdx.y << 5;
    const int tx = tid & 15, ty = tid >> 4;
    const int ix0 = ox0*S - pad, iy0 = oy0*S - pad;
    const int HWin = Hin*Win;
    const float* inb = in + (size_t)n*Cin*HWin;
    const int tx2 = tid & 31, ty2 = tid >> 5;

    auto load_stage = [&](int cib, int buf) {
        #pragma unroll
        for (int cl = 0; cl < CIB; cl++) {
            const float* ip = inb + (size_t)(cib + cl)*HWin;
            float* sp = &sIn[buf][cl*IW*IWP];
            for (int r = ty2; r < IW; r += 8) {
                int gy = iy0 + r;
                bool rowok = (unsigned)gy < (unsigned)Hin;
                const float* rp = ip + (size_t)gy*Win;
                for (int c = tx2; c < IW; c += 32) {
                    int gx = ix0 + c;
                    cp4(sp + r*IWP + c, rp + gx,
                        rowok && ((unsigned)gx < (unsigned)Win));
                }
            }
        }
        for (int i = tid; i < CIB*KK*16; i += 256) {
            int oc = i & 15;
            int rest = i >> 4;
            int kk = rest % KK, cl = rest / KK;
            cp4(&sWt[buf][i], wt + ((size_t)(ocb+oc)*Cin + (cib+cl))*KK + kk, true);
        }
    };

    unsigned long long acc2[8][2][2];
    #pragma unroll
    for (int o = 0; o < 8; o++) {
        acc2[o][0][0] = 0ull; acc2[o][0][1] = 0ull;
        acc2[o][1][0] = 0ull; acc2[o][1][1] = 0ull;
    }

    const int NB = Cin / CIB;
    load_stage(0, 0);
    cp_commit();

    for (int b = 0; b < NB; b++) {
        const int buf = b & 1;
        if (b + 1 < NB) {
            load_stage((b+1)*CIB, buf ^ 1);
            cp_commit();
            cp_wait<1>();
        } else {
            cp_wait<0>();
        }
        __syncthreads();

        #pragma unroll
        for (int cl = 0; cl < CIB; cl++) {
            const float* sI = &sIn[buf][cl*IW*IWP];
            const float* sW = &sWt[buf][cl*KK*16];
            if constexpr (S == 1) {
                unsigned long long inr2[K+1][K+1];
                #pragma unroll
                for (int r = 0; r < K+1; r++)
                    #pragma unroll
                    for (int c = 0; c < K+1; c++) {
                        float v = sI[(ty*2 + r)*IWP + tx*2 + c];
                        inr2[r][c] = f2pack(v, v);
                    }
                #pragma unroll
                for (int ky = 0; ky < K; ky++)
                #pragma unroll
                for (int kx = 0; kx < K; kx++) {
                    const ulonglong2* wp = (const ulonglong2*)(sW + (ky*K + kx)*16);
                    ulonglong2 wa = wp[0], wb = wp[1], wc = wp[2], wd = wp[3];
                    unsigned long long w2[8] = {wa.x, wa.y, wb.x, wb.y,
                                                wc.x, wc.y, wd.x, wd.y};
                    #pragma unroll
                    for (int dy = 0; dy < 2; dy++)
                    #pragma unroll
                    for (int dx = 0; dx < 2; dx++) {
                        unsigned long long s2 = inr2[ky+dy][kx+dx];
                        #pragma unroll
                        for (int o = 0; o < 8; o++)
                            acc2[o][dy][dx] = ffma2(w2[o], s2, acc2[o][dy][dx]);
                    }
                }
            } else {
                #pragma unroll
                for (int ky = 0; ky < K; ky++)
                #pragma unroll
                for (int kx = 0; kx < K; kx++) {
                    const ulonglong2* wp = (const ulonglong2*)(sW + (ky*K + kx)*16);
                    ulonglong2 wa = wp[0], wb = wp[1], wc = wp[2], wd = wp[3];
                    unsigned long long w2[8] = {wa.x, wa.y, wb.x, wb.y,
                                                wc.x, wc.y, wd.x, wd.y};
                    #pragma unroll
                    for (int dy = 0; dy < 2; dy++)
                    #pragma unroll
                    for (int dx = 0; dx < 2; dx++) {
                        float s = sI[((ty*2+dy)*S + ky)*IWP + (tx*2+dx)*S + kx];
                        unsigned long long s2 = f2pack(s, s);
                        #pragma unroll
                        for (int o = 0; o < 8; o++)
                            acc2[o][dy][dx] = ffma2(w2[o], s2, acc2[o][dy][dx]);
                    }
                }
            }
        }
        __syncthreads();
    }

    float acc[16][2][2];
    #pragma unroll
    for (int o = 0; o < 8; o++)
    #pragma unroll
    for (int dy = 0; dy < 2; dy++)
    #pragma unroll
    for (int dx = 0; dx < 2; dx++) {
        float2 f = f2unpack(acc2[o][dy][dx]);
        acc[2*o  ][dy][dx] = f.x;
        acc[2*o+1][dy][dx] = f.y;
    }

    const int oy = oy0 + ty*2, ox = ox0 + tx*2;
    #pragma unroll
    for (int o = 0; o < 16; o++) {
        int c = ocb + o;
        float bv = bias ? __ldg(bias + c) : 0.f;
        #pragma unroll
        for (int dy = 0; dy < 2; dy++)
        #pragma unroll
        for (int dx = 0; dx < 2; dx++) {
            float v = acc[o][dy][dx];
            if (bias)  v = __fadd_rn(v, bv);
            size_t oi = (((size_t)n*Cout + c)*Hout + (oy+dy))*Wout + (ox+dx);
            if (resid) v = __fadd_rn(v, resid[oi]);
            if (act == 1)      v = (v > 0.f) ? v : __fmul_rn(0.01f, v);
            else if (act == 2) v = (v > 0.f) ? v : 0.f;
            out[oi] = v;
        }
    }
}

// ---------------- direct 1x1 convolution (GEMM-style, FFMA2-packed) ----------------
__global__ __launch_bounds__(256)
void conv1x1(const float* __restrict__ in, const float* __restrict__ wt,
             const float* __restrict__ bias, const float* __restrict__ resid,
             float* __restrict__ out,
             int Cin, int HW, int Cout, int act)
{
    __shared__ __align__(16) float sW[128*16];   // [ci][oc], Cin<=128

    const int tid = threadIdx.x;
    const int ocb = blockIdx.y << 4;
    for (int i = tid; i < Cin*16; i += 256) {
        int oc = i & 15, ci = i >> 4;
        sW[i] = __ldg(wt + (size_t)(ocb+oc)*Cin + ci);
    }
    __syncthreads();

    const int gp = (blockIdx.x*256 + tid) * 4;
    const int n = gp / HW, p = gp - n*HW;
    const float* ip = in + ((size_t)n*Cin)*HW + p;

    unsigned long long acc2[8][4];
    #pragma unroll
    for (int o = 0; o < 8; o++)
        #pragma unroll
        for (int j = 0; j < 4; j++) acc2[o][j] = 0ull;

    #pragma unroll 2
    for (int ci = 0; ci < Cin; ci++) {
        float4 xv = *(const float4*)(ip + (size_t)ci*HW);
        unsigned long long xp[4] = { f2pack(xv.x, xv.x), f2pack(xv.y, xv.y),
                                     f2pack(xv.z, xv.z), f2pack(xv.w, xv.w) };
        const ulonglong2* wp = (const ulonglong2*)(sW + ci*16);
        ulonglong2 wa = wp[0], wb = wp[1], wc = wp[2], wd = wp[3];
        unsigned long long w2[8] = {wa.x, wa.y, wb.x, wb.y, wc.x, wc.y, wd.x, wd.y};
        #pragma unroll
        for (int o = 0; o < 8; o++) {
            acc2[o][0] = ffma2(w2[o], xp[0], acc2[o][0]);
            acc2[o][1] = ffma2(w2[o], xp[1], acc2[o][1]);
            acc2[o][2] = ffma2(w2[o], xp[2], acc2[o][2]);
            acc2[o][3] = ffma2(w2[o], xp[3], acc2[o][3]);
        }
    }

    #pragma unroll
    for (int o2 = 0; o2 < 8; o2++) {
        float accl[2][4];
        #pragma unroll
        for (int j = 0; j < 4; j++) {
            float2 f = f2unpack(acc2[o2][j]);
            accl[0][j] = f.x; accl[1][j] = f.y;
        }
        #pragma unroll
        for (int h = 0; h < 2; h++) {
            int c = ocb + 2*o2 + h;
            float bv = bias ? __ldg(bias + c) : 0.f;
            size_t ob = ((size_t)n*Cout + c)*HW + p;
            #pragma unroll
            for (int j = 0; j < 4; j++) {
                float v = accl[h][j];
                if (bias)  v = __fadd_rn(v, bv);
                if (resid) v = __fadd_rn(v, resid[ob + j]);
                if (act == 1)      v = (v > 0.f) ? v : __fmul_rn(0.01f, v);
                else if (act == 2) v = (v > 0.f) ? v : 0.f;
                out[ob + j] = v;
            }
        }
    }
}

// ---------------- pipelined transposed conv (k=4,s=2,p=1), FFMA2-packed ----------------
template<int OCBt, int LOG_OCB, int CIB>
__global__ __launch_bounds__(256, 2)
void convT_pipe(const float* __restrict__ in, const float* __restrict__ wt,
                const float* __restrict__ bias, float* __restrict__ out,
                int N, int Cin, int Hin, int Win, int Cout, int act)
{
    constexpr int IW = 18, IWP = 19;
    constexpr int OP = OCBt/2;   // oc pairs
    __shared__ float sIn[2][CIB*IW*IWP];
    __shared__ __align__(16) float sWt[2][CIB*16*OCBt];

    const int tid = threadIdx.x;
    const int Hout = Hin*2, Wout = Win*2;
    const int chunks = Cout >> LOG_OCB;
    const int n   = blockIdx.z / chunks;
    const int ocb = (blockIdx.z - n*chunks) << LOG_OCB;
    const int ox0 = blockIdx.x << 5, oy0 = blockIdx.y << 5;
    const int tx = tid & 15, ty = tid >> 4;
    const int iyb = (oy0 >> 1) - 1, ixb = (ox0 >> 1) - 1;
    const int HWin = Hin*Win;
    const float* inb = in + (size_t)n*Cin*HWin;
    const int tx2 = tid & 31, ty2 = tid >> 5;

    const int ky0 = 1 - (ty & 1), kx0 = 1 - (tx & 1);
    const int hy = (ty >> 1) + 1 + (ty & 1);
    const int hx = (tx >> 1) + 1 + (tx & 1);

    auto load_stage = [&](int cib, int buf) {
        #pragma unroll
        for (int cl = 0; cl < CIB; cl++) {
            const float* ip = inb + (size_t)(cib + cl)*HWin;
            float* sp = &sIn[buf][cl*IW*IWP];
            for (int r = ty2; r < IW; r += 8) {
                int gy = iyb + r;
                bool rowok = (unsigned)gy < (unsigned)Hin;
                const float* rp = ip + (size_t)gy*Win;
                for (int c = tx2; c < IW; c += 32) {
                    int gx = ixb + c;
                    cp4(sp + r*IWP + c, rp + gx,
                        rowok && ((unsigned)gx < (unsigned)Win));
                }
            }
        }
        for (int i = tid; i < CIB*16*OCBt; i += 256) {
            int oc = i & (OCBt-1);
            int rest = i >> LOG_OCB;
            int kk = rest & 15, cl = rest >> 4;
            cp4(&sWt[buf][i], wt + ((size_t)(cib+cl)*Cout + (ocb+oc))*16 + kk, true);
        }
    };

    unsigned long long acc2[OP][2][2];
    #pragma unroll
    for (int o = 0; o < OP; o++) {
        acc2[o][0][0] = 0ull; acc2[o][0][1] = 0ull;
        acc2[o][1][0] = 0ull; acc2[o][1][1] = 0ull;
    }

    const int NB = Cin / CIB;
    load_stage(0, 0);
    cp_commit();

    for (int b = 0; b < NB; b++) {
        const int buf = b & 1;
        if (b + 1 < NB) {
            load_stage((b+1)*CIB, buf ^ 1);
            cp_commit();
            cp_wait<1>();
        } else {
            cp_wait<0>();
        }
        __syncthreads();

        #pragma unroll
        for (int cl = 0; cl < CIB; cl++) {
            const float* sI = &sIn[buf][cl*IW*IWP];
            const float* sW = &sWt[buf][cl*16*OCBt];

            unsigned long long vin2[2][2][2][2];   // [ey][tap_y][ex][tap_x]
            #pragma unroll
            for (int ey = 0; ey < 2; ey++)
            #pragma unroll
            for (int tyt = 0; tyt < 2; tyt++)
            #pragma unroll
            for (int ex = 0; ex < 2; ex++)
            #pragma unroll
            for (int txt = 0; txt < 2; txt++) {
                float v = sI[(hy + 8*ey - tyt)*IWP + (hx + 8*ex - txt)];
                vin2[ey][tyt][ex][txt] = f2pack(v, v);
            }

            #pragma unroll
            for (int tyt = 0; tyt < 2; tyt++)
            #pragma unroll
            for (int txt = 0; txt < 2; txt++) {
                const int kk = (ky0 + 2*tyt)*4 + (kx0 + 2*txt);
                const unsigned long long* wp =
                    (const unsigned long long*)(sW + kk*OCBt);
                unsigned long long w2[OP];
                #pragma unroll
                for (int j = 0; j < OP; j++) w2[j] = wp[j];
                #pragma unroll
                for (int ey = 0; ey < 2; ey++)
                #pragma unroll
                for (int ex = 0; ex < 2; ex++) {
                    unsigned long long s2 = vin2[ey][tyt][ex][txt];
                    #pragma unroll
                    for (int o = 0; o < OP; o++)
                        acc2[o][ey][ex] = ffma2(w2[o], s2, acc2[o][ey][ex]);
                }
            }
        }
        __syncthreads();
    }

    #pragma unroll
    for (int o2 = 0; o2 < OP; o2++) {
        float accl[2][2][2];
        #pragma unroll
        for (int ey = 0; ey < 2; ey++)
        #pragma unroll
        for (int ex = 0; ex < 2; ex++) {
            float2 f = f2unpack(acc2[o2][ey][ex]);
            accl[0][ey][ex] = f.x; accl[1][ey][ex] = f.y;
        }
        #pragma unroll
        for (int h = 0; h < 2; h++) {
            int c = ocb + 2*o2 + h;
            float bv = bias ? __ldg(bias + c) : 0.f;
            #pragma unroll
            for (int ey = 0; ey < 2; ey++)
            #pragma unroll
            for (int ex = 0; ex < 2; ex++) {
                float v = accl[h][ey][ex];
                if (bias) v = __fadd_rn(v, bv);
                int oy = oy0 + ty + 16*ey, ox = ox0 + tx + 16*ex;
                if (act == 1)      v = (v > 0.f) ? v : __fmul_rn(0.01f, v);
                else if (act == 2) v = (v > 0.f) ? v : 0.f;
                out[(((size_t)n*Cout + c)*Hout + oy)*Wout + ox] = v;
            }
        }
    }
}

// ---------------- RVQ (numerics locked: identical value chains) ----------------
__global__ __launch_bounds__(256)
void cnorm_kernel(const float* __restrict__ cb, float* __restrict__ cn, int total)
{
    int warp = (blockIdx.x*256 + threadIdx.x) >> 5;
    int lane = threadIdx.x & 31;
    if (warp >= total) return;
    const float* p = cb + (size_t)warp*64;
    float a0 = p[lane], a1 = p[lane+32];
    float a = __fadd_rn(__fmul_rn(a0, a0), __fmul_rn(a1, a1));
    #pragma unroll
    for (int off = 16; off > 0; off >>= 1)
        a = __fadd_rn(a, __shfl_down_sync(0xffffffffu, a, off));
    if (lane == 0) cn[warp] = a;
}

// All 4 RVQ stages fused; dot products FFMA2-packed (each half-lane chain identical).
__global__ __launch_bounds__(256)
void rvq_fused(const float* __restrict__ r_in, float* __restrict__ qacc,
               const float* __restrict__ cbs, const float* __restrict__ cnorm,
               float* __restrict__ idx_out, float* __restrict__ partials, int HW)
{
    __shared__ __align__(16) float sCt[64*32];
    __shared__ float sCn[32];
    __shared__ float sRed[256];

    const int t = blockIdx.x*256 + threadIdx.x;
    const int n = t / HW, p = t - n*HW;
    const size_t base = (size_t)n*64*HW + p;

    float rl[64], qa[64];
    #pragma unroll
    for (int d = 0; d < 64; d++)
        rl[d] = r_in[base + (size_t)d*HW];

    for (int stage = 0; stage < 4; stage++) {
        const float* cb = cbs + (size_t)stage*512*64;
        const float* cn = cnorm + stage*512;

        float rn = 0.f;
        #pragma unroll
        for (int d = 0; d < 64; d++) rn = fmaf(rl[d], rl[d], rn);

        float best = 3.4e38f; int bidx = 0;
        for (int kb = 0; kb < 512; kb += 32) {
            __syncthreads();
            for (int i = threadIdx.x; i < 64*32; i += 256) {
                int kk = i & 31, d = i >> 5;
                sCt[i] = __ldg(cb + (size_t)(kb + kk)*64 + d);
            }
            if (threadIdx.x < 32) sCn[threadIdx.x] = cn[kb + threadIdx.x];
            __syncthreads();

            unsigned long long dot2[16];
            #pragma unroll
            for (int j = 0; j < 16; j++) dot2[j] = 0ull;
            #pragma unroll
            for (int d = 0; d < 64; d++) {
                unsigned long long rt2 = f2pack(rl[d], rl[d]);
                const ulonglong2* cp = (const ulonglong2*)(sCt + d*32);
                #pragma unroll
                for (int j4 = 0; j4 < 8; j4++) {
                    ulonglong2 c2 = cp[j4];
                    dot2[j4*2+0] = ffma2(rt2, c2.x, dot2[j4*2+0]);
                    dot2[j4*2+1] = ffma2(rt2, c2.y, dot2[j4*2+1]);
                }
            }
            #pragma unroll
            for (int j2 = 0; j2 < 16; j2++) {
                float2 dd = f2unpack(dot2[j2]);
                float dist0 = __fadd_rn(__fadd_rn(rn, -__fmul_rn(2.f, dd.x)), sCn[2*j2]);
                if (dist0 < best) { best = dist0; bidx = kb + 2*j2; }
                float dist1 = __fadd_rn(__fadd_rn(rn, -__fmul_rn(2.f, dd.y)), sCn[2*j2+1]);
                if (dist1 < best) { best = dist1; bidx = kb + 2*j2 + 1; }
            }
        }

        float lsum = 0.f;
        const float* cq = cb + (size_t)bidx*64;
        #pragma unroll
        for (int d = 0; d < 64; d++) {
            float q = __ldg(cq + d);
            float diff = __fadd_rn(q, -rl[d]);
            lsum = fmaf(diff, diff, lsum);
            float q_st = __fadd_rn(rl[d], diff);
            if (stage == 0) qa[d] = q_st;
            else            qa[d] = __fadd_rn(qa[d], q_st);
            rl[d] = __fadd_rn(rl[d], -q);
        }
        idx_out[(size_t)t*4 + stage] = (float)bidx;

        __syncthreads();
        sRed[threadIdx.x] = lsum;
        __syncthreads();
        for (int sft = 128; sft > 0; sft >>= 1) {
            if (threadIdx.x < sft) sRed[threadIdx.x] += sRed[threadIdx.x + sft];
            __syncthreads();
        }
        if (threadIdx.x == 0) partials[stage*256 + blockIdx.x] = sRed[0];
    }

    #pragma unroll
    for (int d = 0; d < 64; d++)
        qacc[base + (size_t)d*HW] = qa[d];
}

__global__ __launch_bounds__(256)
void loss_finalize(const float* __restrict__ partials, float* __restrict__ loss_out, float scale)
{
    __shared__ float sRed[256];
    int stage = blockIdx.x;
    sRed[threadIdx.x] = partials[stage*256 + threadIdx.x];
    __syncthreads();
    for (int sft = 128; sft > 0; sft >>= 1) {
        if (threadIdx.x < sft) sRed[threadIdx.x] += sRed[threadIdx.x + sft];
        __syncthreads();
    }
    if (threadIdx.x == 0) loss_out[stage] = 0.25f * (sRed[0] * scale);
}

// ---------------- launch ----------------
extern "C" void kernel_launch(void* const* d_in, const int* in_sizes, int n_in,
                              void* d_out, int out_size)
{
    const float* x     = (const float*)d_in[0];
    const float* e1w   = (const float*)d_in[1];
    const float* e1b   = (const float*)d_in[2];
    const float* e2w   = (const float*)d_in[3];
    const float* e2b   = (const float*)d_in[4];
    const float* e3w   = (const float*)d_in[5];
    const float* e3b   = (const float*)d_in[6];
    const float* r1aw  = (const float*)d_in[7];
    const float* r1bw  = (const float*)d_in[8];
    const float* r2aw  = (const float*)d_in[9];
    const float* r2bw  = (const float*)d_in[10];
    const float* e4w   = (const float*)d_in[11];
    const float* e4b   = (const float*)d_in[12];
    const float* cbs   = (const float*)d_in[13];
    const float* d1w   = (const float*)d_in[14];
    const float* d1b   = (const float*)d_in[15];
    const float* dr1aw = (const float*)d_in[16];
    const float* dr1bw = (const float*)d_in[17];
    const float* dr2aw = (const float*)d_in[18];
    const float* dr2bw = (const float*)d_in[19];
    const float* dt1w  = (const float*)d_in[20];
    const float* dt1b  = (const float*)d_in[21];
    const float* dt2w  = (const float*)d_in[22];
    const float* dt2b  = (const float*)d_in[23];

    float* out = (float*)d_out;
    float* recons  = out;                        // 16*4*256*256
    float* idxout  = out + (size_t)16*4*256*256; // 16*64*64*4
    float* lossout = idxout + (size_t)16*64*64*4;// 4

    float *A,*B,*C,*D,*R,*Q,*CN,*P;
    cudaGetSymbolAddress((void**)&A,  g_bufA);
    cudaGetSymbolAddress((void**)&B,  g_bufB);
    cudaGetSymbolAddress((void**)&C,  g_bufC);
    cudaGetSymbolAddress((void**)&D,  g_bufD);
    cudaGetSymbolAddress((void**)&R,  g_r);
    cudaGetSymbolAddress((void**)&Q,  g_q);
    cudaGetSymbolAddress((void**)&CN, g_cnorm);
    cudaGetSymbolAddress((void**)&P,  g_partials);

    cnorm_kernel<<<256, 256>>>(cbs, CN, 4*512);

    // ---- encoder (fp32, numerics locked) ----
    conv_pipe<4,2,1><<<dim3(4,4,64), 256>>>(x, e1w, e1b, nullptr, A,
                                            16,4,256,256, 64,128,128, 1, 1);
    conv_pipe<4,2,1><<<dim3(2,2,128), 256>>>(A, e2w, e2b, nullptr, B,
                                             16,64,128,128, 128,64,64, 1, 1);
    conv_pipe<3,1,4><<<dim3(2,2,128), 256>>>(B, e3w, e3b, nullptr, C,
                                             16,128,64,64, 128,64,64, 1, 1);
    conv_pipe<3,1,4><<<dim3(2,2,128), 256>>>(C, r1aw, nullptr, nullptr, D,
                                             16,128,64,64, 128,64,64, 1, 2);
    conv1x1<<<dim3(64,8), 256>>>(D, r1bw, nullptr, C, B, 128, 4096, 128, 0);
    conv_pipe<3,1,4><<<dim3(2,2,128), 256>>>(B, r2aw, nullptr, nullptr, D,
                                             16,128,64,64, 128,64,64, 1, 2);
    conv1x1<<<dim3(64,8), 256>>>(D, r2bw, nullptr, B, C, 128, 4096, 128, 1);
    conv1x1<<<dim3(64,4), 256>>>(C, e4w, e4b, nullptr, R, 128, 4096, 64, 1);

    // ---- residual VQ: 4 stages fused ----
    rvq_fused<<<256, 256>>>(R, Q, cbs, CN, idxout, P, 64*64);
    loss_finalize<<<4, 256>>>(P, lossout, 1.f/(65536.f*64.f));

    // ---- decoder (fp32, numerics locked) ----
    conv_pipe<3,1,4><<<dim3(2,2,128), 256>>>(Q, d1w, d1b, nullptr, B,
                                             16,64,64,64, 128,64,64, 1, 1);
    conv_pipe<3,1,4><<<dim3(2,2,128), 256>>>(B, dr1aw, nullptr, nullptr, D,
                                             16,128,64,64, 128,64,64, 1, 2);
    conv1x1<<<dim3(64,8), 256>>>(D, dr1bw, nullptr, B, C, 128, 4096, 128, 0);
    conv_pipe<3,1,4><<<dim3(2,2,128), 256>>>(C, dr2aw, nullptr, nullptr, D,
                                             16,128,64,64, 128,64,64, 1, 2);
    conv1x1<<<dim3(64,8), 256>>>(D, dr2bw, nullptr, C, B, 128, 4096, 128, 1);
    convT_pipe<16,4,8><<<dim3(4,4,64), 256>>>(B, dt1w, dt1b, A,
                                              16,128,64,64, 64, 1);
    convT_pipe<4,2,8><<<dim3(8,8,16), 256>>>(A, dt2w, dt2b, recons,
                                             16,64,128,128, 4, 2);
}